// round 14
// baseline (speedup 1.0000x reference)
#include <cuda_runtime.h>
#include <cuda_bf16.h>
#include <cstdint>

#define EPSF 1e-5f
#define EPS2F 1e-10f
#define MAXNF (1.0f - 1e-5f)
#define EPSD 1e-5
#define MAXND (1.0 - 1e-5)

constexpr int Bb = 4, Ss = 512, Ee = 512, Hh = 8, Dd = 64;
constexpr int NROW = Bb * Ss;   // 2048
constexpr int BH = Bb * Hh;     // 32

// ---------------- scratch ----------------
__device__ float g_t[3 * NROW * Ee];
__device__ float g_c[3 * NROW];
__device__ __nv_bfloat16 g_Xh[3 * NROW * Ee];
__device__ __nv_bfloat16 g_Xl[3 * NROW * Ee];
__device__ __nv_bfloat16 g_Wh[4 * Ee * Ee];
__device__ __nv_bfloat16 g_Wl[4 * Ee * Ee];
__device__ __nv_bfloat16 g_Qh[BH * Ss * Dd];
__device__ __nv_bfloat16 g_Ql[BH * Ss * Dd];
__device__ __nv_bfloat16 g_Kh[BH * Ss * Dd];
__device__ __nv_bfloat16 g_Kl[BH * Ss * Dd];
__device__ float g_V[BH * Ss * Dd];
__device__ float g_qn[BH * Ss];
__device__ float g_kn[BH * Ss];
__device__ float g_Vn[BH * Ss];
__device__ float g_rsum[BH * Ss];
__device__ float g_attnT[(size_t)BH * Ss * Ss];   // [bh][k][q], UNNORMALIZED exp
__device__ float g_att[NROW * Ee];
__device__ float g_pb[4 * Ee];
__device__ float g_byn[4];

// ---------------- reduction helpers (128 threads) ----------------
__device__ __forceinline__ float blockReduceSum128(float v, float* sbuf) {
    #pragma unroll
    for (int o = 16; o > 0; o >>= 1) v += __shfl_xor_sync(0xffffffffu, v, o);
    if ((threadIdx.x & 31) == 0) sbuf[threadIdx.x >> 5] = v;
    __syncthreads();
    float r = sbuf[0] + sbuf[1] + sbuf[2] + sbuf[3];
    __syncthreads();
    return r;
}

__device__ __forceinline__ double blockReduceSumD(double v, double* sbuf) {
    #pragma unroll
    for (int o = 16; o > 0; o >>= 1) v += __shfl_xor_sync(0xffffffffu, v, o);
    if ((threadIdx.x & 31) == 0) sbuf[threadIdx.x >> 5] = v;
    __syncthreads();
    double r = sbuf[0] + sbuf[1] + sbuf[2] + sbuf[3];
    __syncthreads();
    return r;
}

__device__ __forceinline__ float fsqrt_fast(float x) {
    float t = fmaxf(x, EPS2F);
    return t * rsqrtf(t);
}

// ---------------- mma.sync helpers ----------------
__device__ __forceinline__ void ldsm4(uint32_t* r, uint32_t addr) {
    asm volatile("ldmatrix.sync.aligned.m8n8.x4.shared.b16 {%0,%1,%2,%3}, [%4];"
        : "=r"(r[0]), "=r"(r[1]), "=r"(r[2]), "=r"(r[3]) : "r"(addr));
}
__device__ __forceinline__ void mma16816(float* d, const uint32_t* a, uint32_t b0, uint32_t b1) {
    asm volatile("mma.sync.aligned.m16n8k16.row.col.f32.bf16.bf16.f32 "
        "{%0,%1,%2,%3}, {%4,%5,%6,%7}, {%8,%9}, {%0,%1,%2,%3};"
        : "+f"(d[0]), "+f"(d[1]), "+f"(d[2]), "+f"(d[3])
        : "r"(a[0]), "r"(a[1]), "r"(a[2]), "r"(a[3]), "r"(b0), "r"(b1));
}

__device__ __forceinline__ void cvt_hilo(float4 f, __nv_bfloat162& h01, __nv_bfloat162& h23,
                                         __nv_bfloat162& l01, __nv_bfloat162& l23) {
    h01 = __floats2bfloat162_rn(f.x, f.y);
    h23 = __floats2bfloat162_rn(f.z, f.w);
    l01 = __floats2bfloat162_rn(f.x - __bfloat162float(h01.x), f.y - __bfloat162float(h01.y));
    l23 = __floats2bfloat162_rn(f.z - __bfloat162float(h23.x), f.w - __bfloat162float(h23.y));
}

// ---------------- prep_all ----------------
__global__ void prep_all(const float* __restrict__ q, const float* __restrict__ k,
                         const float* __restrict__ v,
                         const float* __restrict__ Wq, const float* __restrict__ Wk,
                         const float* __restrict__ Wv, const float* __restrict__ Wo,
                         const float* __restrict__ bq, const float* __restrict__ bk,
                         const float* __restrict__ bv, const float* __restrict__ bo) {
    __shared__ double sbufd[4];
    __shared__ float sbuff[4];
    int bx = blockIdx.x, tid = threadIdx.x;
    if (bx < 6144) {
        int z = bx >> 11, row = bx & 2047;
        const float* x = z == 0 ? q : z == 1 ? k : v;
        float4 f = ((const float4*)(x + (size_t)row * Ee))[tid];
        double ssp = (double)f.x * f.x + (double)f.y * f.y + (double)f.z * f.z + (double)f.w * f.w;
        double ss1 = blockReduceSumD(ssp, sbufd);
        double n1 = sqrt(fmax(ss1, 1e-10));
        double s1 = (n1 >= MAXND) ? MAXND / (n1 + EPSD) : 1.0;
        double ss2 = s1 * s1 * ss1;
        double n2 = sqrt(fmax(ss2, 1e-10));
        double s2 = (n2 >= MAXND) ? MAXND / (n2 + EPSD) : 1.0;
        double ss3 = s2 * s2 * ss2;
        double n = sqrt(fmax(ss3, 1e-10));
        double ff = (1.0 + EPSD) * atanh(n) / n;
        if (tid == 0) g_c[z * NROW + row] = (float)(ff * s2 * s1);
        __nv_bfloat162 h01, h23, l01, l23;
        cvt_hilo(f, h01, h23, l01, l23);
        size_t off = ((size_t)z * NROW + row) * Ee + tid * 4;
        *(__nv_bfloat162*)(g_Xh + off) = h01; *(__nv_bfloat162*)(g_Xh + off + 2) = h23;
        *(__nv_bfloat162*)(g_Xl + off) = l01; *(__nv_bfloat162*)(g_Xl + off + 2) = l23;
    } else if (bx < 8192) {
        int idx = bx - 6144;
        int w = idx >> 9, r = idx & 511;
        const float* W = w == 0 ? Wq : w == 1 ? Wk : w == 2 ? Wv : Wo;
        float4 f = ((const float4*)(W + (size_t)r * Ee))[tid];
        __nv_bfloat162 h01, h23, l01, l23;
        cvt_hilo(f, h01, h23, l01, l23);
        size_t off = ((size_t)w * Ee + r) * Ee + tid * 4;
        *(__nv_bfloat162*)(g_Wh + off) = h01; *(__nv_bfloat162*)(g_Wh + off + 2) = h23;
        *(__nv_bfloat162*)(g_Wl + off) = l01; *(__nv_bfloat162*)(g_Wl + off + 2) = l23;
    } else {
        int b = bx - 8192;
        const float* bp = b == 0 ? bq : b == 1 ? bk : b == 2 ? bv : bo;
        float4 vv = ((const float4*)bp)[tid];
        float ss = vv.x * vv.x + vv.y * vv.y + vv.z * vv.z + vv.w * vv.w;
        ss = blockReduceSum128(ss, sbuff);
        float norm = sqrtf(fmaxf(ss, EPS2F));
        float s1 = (norm >= MAXNF) ? MAXNF / (norm + EPSF) : 1.0f;
        float4 p; p.x = s1 * vv.x; p.y = s1 * vv.y; p.z = s1 * vv.z; p.w = s1 * vv.w;
        ((float4*)(g_pb + b * Ee))[tid] = p;
        float ss2 = p.x * p.x + p.y * p.y + p.z * p.z + p.w * p.w;
        ss2 = blockReduceSum128(ss2, sbuff);
        if (tid == 0) g_byn[b] = ss2;
    }
}

// ---------------- prep_att ----------------
__global__ void prep_att() {
    __shared__ double sbuf[4];
    int row = blockIdx.x, tid = threadIdx.x;
    float4 f = ((const float4*)(g_att + (size_t)row * Ee))[tid];
    double ssp = (double)f.x * f.x + (double)f.y * f.y + (double)f.z * f.z + (double)f.w * f.w;
    double ss1 = blockReduceSumD(ssp, sbuf);
    double n1 = sqrt(fmax(ss1, 1e-10));
    double s1 = (n1 >= MAXND) ? MAXND / (n1 + EPSD) : 1.0;
    double ss2 = s1 * s1 * ss1;
    double n2 = sqrt(fmax(ss2, 1e-10));
    double s2 = (n2 >= MAXND) ? MAXND / (n2 + EPSD) : 1.0;
    double ss3 = s2 * s2 * ss2;
    double n = sqrt(fmax(ss3, 1e-10));
    double ff = (1.0 + EPSD) * atanh(n) / n;
    if (tid == 0) g_c[row] = (float)(ff * s2 * s1);
    __nv_bfloat162 h01, h23, l01, l23;
    cvt_hilo(f, h01, h23, l01, l23);
    size_t off = (size_t)row * Ee + tid * 4;
    *(__nv_bfloat162*)(g_Xh + off) = h01; *(__nv_bfloat162*)(g_Xh + off + 2) = h23;
    *(__nv_bfloat162*)(g_Xl + off) = l01; *(__nv_bfloat162*)(g_Xl + off + 2) = l23;
}

// ---------------- tensor-core GEMM: 64x128 CTA tile, warp 32x32, 2 CTAs/SM ----------------
constexpr int SPAD = 40;
constexpr int GA_H = 0;
constexpr int GA_L = 64 * SPAD;
constexpr int GB_H = 128 * SPAD;
constexpr int GB_L = 256 * SPAD;

__global__ __launch_bounds__(256, 2) void gemm_mma(int final) {
    __shared__ __align__(16) __nv_bfloat16 sm[384 * SPAD];   // 30720 B

    int tid = threadIdx.x, wid = tid >> 5, lane = tid & 31;
    int z = blockIdx.z;
    int wsel = final ? 3 : z;
    float* T = g_t + (size_t)z * NROW * Ee;
    int n0 = blockIdx.x * 128;
    int m0 = blockIdx.y * 64;

    int wm = wid & 1;
    int wn = wid >> 1;

    float d[2][4][4];
    #pragma unroll
    for (int i = 0; i < 2; i++)
        #pragma unroll
        for (int j = 0; j < 4; j++)
            #pragma unroll
            for (int r = 0; r < 4; r++) d[i][j][r] = 0.0f;

    int rowB = tid & 127;
    const __nv_bfloat16* srcB = ((tid >> 7) ? g_Wl : g_Wh) +
                                ((size_t)wsel * Ee + n0 + rowB) * Ee;
    uint32_t dstB = GB_H + (uint32_t)(tid >> 7) * (128 * SPAD) + rowB * SPAD;
    bool hasA = tid < 128;
    int rowA = tid & 63;
    const __nv_bfloat16* srcA = (((tid >> 6) & 1) ? g_Xl : g_Xh) +
                                ((size_t)z * NROW + m0 + rowA) * Ee;
    uint32_t dstA = (uint32_t)((tid >> 6) & 1) * (64 * SPAD) + rowA * SPAD;

    uint32_t smb = (uint32_t)__cvta_generic_to_shared(sm);
    int lrow = lane & 15;
    int lk8  = (lane >> 4) << 3;

    uint4 rbB[4], rbA[4];
    #pragma unroll
    for (int j = 0; j < 4; j++) rbB[j] = ((const uint4*)srcB)[j];
    if (hasA) {
        #pragma unroll
        for (int j = 0; j < 4; j++) rbA[j] = ((const uint4*)srcA)[j];
    }

    for (int c = 0; c < 16; c++) {
        __syncthreads();
        #pragma unroll
        for (int j = 0; j < 4; j++) *(uint4*)&sm[dstB + j * 8] = rbB[j];
        if (hasA) {
            #pragma unroll
            for (int j = 0; j < 4; j++) *(uint4*)&sm[dstA + j * 8] = rbA[j];
        }
        __syncthreads();
        if (c < 15) {
            #pragma unroll
            for (int j = 0; j < 4; j++) rbB[j] = ((const uint4*)srcB)[(c + 1) * 4 + j];
            if (hasA) {
                #pragma unroll
                for (int j = 0; j < 4; j++) rbA[j] = ((const uint4*)srcA)[(c + 1) * 4 + j];
            }
        }
        #pragma unroll
        for (int ks = 0; ks < 2; ks++) {
            int kcol = ks * 16 + lk8;
            uint32_t ah[2][4], al[2][4], bh[2][4], bl[2][4];
            #pragma unroll
            for (int i = 0; i < 2; i++) {
                ldsm4(ah[i], smb + 2 * (GA_H + (wm * 32 + i * 16 + lrow) * SPAD + kcol));
                ldsm4(al[i], smb + 2 * (GA_L + (wm * 32 + i * 16 + lrow) * SPAD + kcol));
            }
            #pragma unroll
            for (int t = 0; t < 2; t++) {
                ldsm4(bh[t], smb + 2 * (GB_H + (wn * 32 + t * 16 + lrow) * SPAD + kcol));
                ldsm4(bl[t], smb + 2 * (GB_L + (wn * 32 + t * 16 + lrow) * SPAD + kcol));
            }
            #pragma unroll
            for (int i = 0; i < 2; i++)
                #pragma unroll
                for (int j = 0; j < 4; j++) {
                    uint32_t b0h = bh[j >> 1][j & 1], b1h = bh[j >> 1][(j & 1) + 2];
                    mma16816(d[i][j], ah[i], b0h, b1h);
                    mma16816(d[i][j], ah[i], bl[j >> 1][j & 1], bl[j >> 1][(j & 1) + 2]);
                    mma16816(d[i][j], al[i], b0h, b1h);
                }
        }
    }
    #pragma unroll
    for (int i = 0; i < 2; i++) {
        int gr = m0 + wm * 32 + i * 16 + (lane >> 2);
        #pragma unroll
        for (int j = 0; j < 4; j++) {
            int gc = n0 + wn * 32 + j * 8 + (lane & 3) * 2;
            *(float2*)&T[(size_t)gr * Ee + gc]       = make_float2(d[i][j][0], d[i][j][1]);
            *(float2*)&T[(size_t)(gr + 8) * Ee + gc] = make_float2(d[i][j][2], d[i][j][3]);
        }
    }
}

// ---------------- epilogue ----------------
__global__ void epilogue(int final, float* __restrict__ out) {
    __shared__ float sbuf[4];
    int row = blockIdx.x;
    int z = blockIdx.y;
    int tid = threadIdx.x;
    int mode = final ? 0 : z + 1;
    int bidx = final ? 3 : z;
    float c = g_c[z * NROW + row];
    float4 t4 = ((const float4*)(g_t + ((size_t)z * NROW + row) * Ee))[tid];
    t4.x *= c; t4.y *= c; t4.z *= c; t4.w *= c;

    float ss_t = t4.x * t4.x + t4.y * t4.y + t4.z * t4.z + t4.w * t4.w;
    ss_t = blockReduceSum128(ss_t, sbuf);
    float n = fsqrt_fast(ss_t);
    float gg = tanhf(n / (1.0f + EPSF)) * __fdividef(1.0f, n);
    float ss_v = gg * gg * ss_t;
    float nv = fsqrt_fast(ss_v);
    float sr = (nv >= MAXNF) ? MAXNF * __fdividef(1.0f, nv + EPSF) : 1.0f;
    float ss_r = sr * sr * ss_v;
    float nr = fsqrt_fast(ss_r);
    float sx = (nr >= MAXNF) ? MAXNF * __fdividef(1.0f, nr + EPSF) : 1.0f;
    float xn = sx * sx * ss_r;
    float m = gg * sr * sx;

    float4 v4; v4.x = m * t4.x; v4.y = m * t4.y; v4.z = m * t4.z; v4.w = m * t4.w;
    float4 p4 = ((const float4*)(g_pb + bidx * Ee))[tid];
    float xyp = v4.x * p4.x + v4.y * p4.y + v4.z * p4.z + v4.w * p4.w;
    float xy = blockReduceSum128(xyp, sbuf);
    float yn = g_byn[bidx];

    float A = 1.0f + 2.0f * xy + yn;
    float Bc = 1.0f - xn;
    float rden = __fdividef(1.0f, 1.0f + 2.0f * xy + xn * yn + EPSF);
    float4 u4;
    u4.x = (A * v4.x + Bc * p4.x) * rden;
    u4.y = (A * v4.y + Bc * p4.y) * rden;
    u4.z = (A * v4.z + Bc * p4.z) * rden;
    u4.w = (A * v4.w + Bc * p4.w) * rden;

    float ss_u = u4.x * u4.x + u4.y * u4.y + u4.z * u4.z + u4.w * u4.w;
    ss_u = blockReduceSum128(ss_u, sbuf);
    float nu = fsqrt_fast(ss_u);
    float so = (nu >= MAXNF) ? MAXNF * __fdividef(1.0f, nu + EPSF) : 1.0f;
    u4.x *= so; u4.y *= so; u4.z *= so; u4.w *= so;

    if (mode == 0) {
        ((float4*)(out + (size_t)row * Ee))[tid] = u4;
        return;
    }
    float hs = u4.x * u4.x + u4.y * u4.y + u4.z * u4.z + u4.w * u4.w;
    #pragma unroll
    for (int o = 8; o > 0; o >>= 1) hs += __shfl_xor_sync(0xffffffffu, hs, o);
    int h = tid >> 4;
    int bI = row >> 9, sI = row & 511;
    int bh = bI * Hh + h;
    size_t base = ((size_t)bh * Ss + sI) * Dd + (tid & 15) * 4;
    if (mode == 3) {
        *(float4*)(g_V + base) = u4;
        if ((tid & 15) == 0) g_Vn[bh * Ss + sI] = hs;
    } else {
        float nh = fsqrt_fast(hs);
        float sh = (nh >= MAXNF) ? MAXNF * __fdividef(1.0f, nh + EPSF) : 1.0f;
        float4 q4; q4.x = sh * u4.x; q4.y = sh * u4.y; q4.z = sh * u4.z; q4.w = sh * u4.w;
        __nv_bfloat162 h01, h23, l01, l23;
        cvt_hilo(q4, h01, h23, l01, l23);
        __nv_bfloat16* dh = (mode == 1 ? g_Qh : g_Kh) + base;
        __nv_bfloat16* dl = (mode == 1 ? g_Ql : g_Kl) + base;
        *(__nv_bfloat162*)dh = h01; *(__nv_bfloat162*)(dh + 2) = h23;
        *(__nv_bfloat162*)dl = l01; *(__nv_bfloat162*)(dl + 2) = l23;
        float* ndst = (mode == 1) ? g_qn : g_kn;
        if ((tid & 15) == 0) ndst[bh * Ss + sI] = sh * sh * hs;
    }
}

// ---------------- attention: register-S MMA distances + online softmax ----------------
constexpr int QPAD = 72;
constexpr int AOFF_QH = 0;
constexpr int AOFF_QL = 4608;
constexpr int AOFF_KH = 9216;
constexpr int AOFF_KL = 27648;
constexpr int AOFF_KN = 46080;
constexpr int AOFF_QN = 48128;
constexpr int AOFF_RED = 48256;
constexpr int SMEM_ATTN_BYTES = 49280;

__global__ __launch_bounds__(256, 2) void attn_kernel() {
    extern __shared__ char smc[];
    __nv_bfloat16* Kh = (__nv_bfloat16*)(smc + AOFF_KH);
    __nv_bfloat16* Kl = (__nv_bfloat16*)(smc + AOFF_KL);
    float* Pst = (float*)(smc + AOFF_KH);
    float* knS = (float*)(smc + AOFF_KN);
    float* qnS = (float*)(smc + AOFF_QN);
    float* RED = (float*)(smc + AOFF_RED);

    int bh = blockIdx.x >> 4, qt = blockIdx.x & 15;
    int tid = threadIdx.x, wid = tid >> 5, lane = tid & 31;
    int lrow = lane & 15, lk8 = (lane >> 4) << 3;

    for (int i = tid; i < 512; i += 256) knS[i] = g_kn[bh * Ss + i];
    if (tid < 32) qnS[tid] = g_qn[bh * Ss + qt * 32 + tid];

    #pragma unroll
    for (int it = 0; it < 2; it++) {
        int u = tid + it * 256;
        int mat = u >> 8, row = (u >> 3) & 31, c16 = u & 7;
        const uint4* src = (const uint4*)((mat ? g_Ql : g_Qh) +
                            ((size_t)bh * Ss + qt * 32 + row) * Dd) + c16;
        *(uint4*)(smc + (mat ? AOFF_QL : AOFF_QH) + 2 * (row * QPAD + c16 * 8)) = *src;
    }
    __syncthreads();

    uint32_t smb = (uint32_t)__cvta_generic_to_shared(smc);

    uint32_t Ah[2][4][4];
    #pragma unroll
    for (int mm = 0; mm < 2; mm++)
        #pragma unroll
        for (int k = 0; k < 4; k++)
            ldsm4(Ah[mm][k], smb + AOFF_QH + 2 * ((mm * 16 + lrow) * QPAD + k * 16 + lk8));

    float S[4][2][2][4];

    for (int c = 0; c < 4; c++) {
        __syncthreads();
        #pragma unroll
        for (int it = 0; it < 8; it++) {
            int u = tid + it * 256;
            int mat = u >> 10, row = (u >> 3) & 127, c16 = u & 7;
            const uint4* src = (const uint4*)((mat ? g_Kl : g_Kh) +
                                ((size_t)bh * Ss + c * 128 + row) * Dd) + c16;
            *(uint4*)((mat ? Kl : Kh) + row * QPAD + c16 * 8) = *src;
        }
        __syncthreads();

        #pragma unroll
        for (int mm = 0; mm < 2; mm++)
            #pragma unroll
            for (int j = 0; j < 2; j++)
                #pragma unroll
                for (int r = 0; r < 4; r++) S[c][mm][j][r] = 0.0f;

        #pragma unroll
        for (int k = 0; k < 4; k++) {
            uint32_t Bh[4], Bl[4];
            ldsm4(Bh, smb + AOFF_KH + 2 * ((wid * 16 + lrow) * QPAD + k * 16 + lk8));
            ldsm4(Bl, smb + AOFF_KL + 2 * ((wid * 16 + lrow) * QPAD + k * 16 + lk8));
            #pragma unroll
            for (int mm = 0; mm < 2; mm++) {
                uint32_t Alf[4];
                ldsm4(Alf, smb + AOFF_QL + 2 * ((mm * 16 + lrow) * QPAD + k * 16 + lk8));
                #pragma unroll
                for (int j = 0; j < 2; j++) {
                    mma16816(S[c][mm][j], Ah[mm][k], Bh[j], Bh[j + 2]);
                    mma16816(S[c][mm][j], Ah[mm][k], Bl[j], Bl[j + 2]);
                    mma16816(S[c][mm][j], Alf, Bh[j], Bh[j + 2]);
                }
            }
        }
    }

    float qn4[4];
    #pragma unroll
    for (int g = 0; g < 4; g++)
        qn4[g] = qnS[(g >> 1) * 16 + (g & 1) * 8 + (lane >> 2)];
    #pragma unroll
    for (int c = 0; c < 4; c++)
        #pragma unroll
        for (int mm = 0; mm < 2; mm++)
            #pragma unroll
            for (int j = 0; j < 2; j++)
                #pragma unroll
                for (int r = 0; r < 4; r++) {
                    int kk = c * 128 + wid * 16 + j * 8 + (lane & 3) * 2 + (r & 1);
                    float qn = qn4[mm * 2 + (r >> 1)];
                    float kn = knS[kk];
                    float num = fmaxf(qn + kn - 2.0f * S[c][mm][j][r], 0.0f);
                    float den = fmaxf((1.0f - qn) * (1.0f - kn), EPSF);
                    float dd2 = 2.0f * __fdividef(num, den) + EPSF;
                    float s = dd2 * (2.0f + dd2);
                    float sq = s * rsqrtf(fmaxf(s, 1e-30f));
                    S[c][mm][j][r] = -__logf(1.0f + dd2 + sq);
                }

    float mrow[4];
    #pragma unroll
    for (int g = 0; g < 4; g++) {
        int mm = g >> 1, rh = g & 1;
        float ml = -1e30f;
        #pragma unroll
        for (int c = 0; c < 4; c++)
            #pragma unroll
            for (int j = 0; j < 2; j++) {
                ml = fmaxf(ml, S[c][mm][j][rh * 2]);
                ml = fmaxf(ml, S[c][mm][j][rh * 2 + 1]);
            }
        ml = fmaxf(ml, __shfl_xor_sync(0xffffffffu, ml, 1));
        ml = fmaxf(ml, __shfl_xor_sync(0xffffffffu, ml, 2));
        if ((lane & 3) == 0) RED[(mm * 16 + rh * 8 + (lane >> 2)) * 8 + wid] = ml;
    }
    __syncthreads();
    #pragma unroll
    for (int g = 0; g < 4; g++) {
        int row = (g >> 1) * 16 + (g & 1) * 8 + (lane >> 2);
        float m = RED[row * 8];
        #pragma unroll
        for (int w = 1; w < 8; w++) m = fmaxf(m, RED[row * 8 + w]);
        mrow[g] = m;
    }
    __syncthreads();

    float srow[4] = {0.f, 0.f, 0.f, 0.f};
    #pragma unroll
    for (int c = 0; c < 4; c++)
        #pragma unroll
        for (int mm = 0; mm < 2; mm++)
            #pragma unroll
            for (int j = 0; j < 2; j++)
                #pragma unroll
                for (int r = 0; r < 4; r++) {
                    int g = mm * 2 + (r >> 1);
                    float e = __expf(S[c][mm][j][r] - mrow[g]);
                    S[c][mm][j][r] = e;
                    srow[g] += e;
                }
    #pragma unroll
    for (int g = 0; g < 4; g++) {
        float sv = srow[g];
        sv += __shfl_xor_sync(0xffffffffu, sv, 1);
        sv += __shfl_xor_sync(0xffffffffu, sv, 2);
        if ((lane & 3) == 0) RED[((g >> 1) * 16 + (g & 1) * 8 + (lane >> 2)) * 8 + wid] = sv;
    }
    __syncthreads();
    if (wid == 0 && (lane & 3) == 0) {
        #pragma unroll
        for (int g = 0; g < 4; g++) {
            int row = (g >> 1) * 16 + (g & 1) * 8 + (lane >> 2);
            float sv = 0.f;
            #pragma unroll
            for (int w = 0; w < 8; w++) sv += RED[row * 8 + w];
            g_rsum[bh * Ss + qt * 32 + row] = sv;
        }
    }

    float* Og = g_attnT + (size_t)bh * Ss * Ss + qt * 32;
    for (int c = 0; c < 4; c++) {
        __syncthreads();
        #pragma unroll
        for (int mm = 0; mm < 2; mm++)
            #pragma unroll
            for (int j = 0; j < 2; j++)
                #pragma unroll
                for (int r = 0; r < 4; r++) {
                    int kk = wid * 16 + j * 8 + (lane & 3) * 2 + (r & 1);
                    int qi = mm * 16 + (lane >> 2) + 8 * (r >> 1);
                    Pst[kk * 36 + qi] = S[c][mm][j][r];
                }
        __syncthreads();
        #pragma unroll
        for (int i = 0; i < 16; i++) {
            int kkr = wid * 16 + i;
            Og[(size_t)(c * 128 + kkr) * Ss + lane] = Pst[kkr * 36 + lane];
        }
    }
}

// ---------------- scan v4: 4 thr/row, 512-thr blocks (4 warps/SMSP) ----------------
// grid 128: block = (bh, 128-q chunk). Thread owns 16 dims; quad = one row.
__global__ __launch_bounds__(512) void scan_kernel() {
    __shared__ float sV[32 * 68];
    __shared__ float sW[32 * 132];
    __shared__ float sVn[32];
    __shared__ float sVnS[32];
    int tid = threadIdx.x;
    int warp = tid >> 5, lane = tid & 31;
    int qrow = (warp << 3) + (lane >> 2);   // 0..127
    int sub = lane & 3;                     // 16-dim slice
    int bh = blockIdx.x >> 2, qt = blockIdx.x & 3;
    int q0 = qt * 128;
    const float* Vg = g_V + (size_t)bh * Ss * Dd;
    const float* Wg = g_attnT + (size_t)bh * Ss * Ss + q0;

    float rinv = __fdividef(1.0f, g_rsum[bh * Ss + q0 + qrow]);

    float ws[16];
    #pragma unroll
    for (int i = 0; i < 16; i++) ws[i] = 0.0f;
    float ssn = 0.0f;   // ||ws||^2 (ws stored UNPROJECTED; entry proj via sx)

    for (int jt = 0; jt < 16; jt++) {
        __syncthreads();
        {   // sV: 512 float4 / 512 thr
            int j = tid >> 4, d4 = tid & 15;
            float4 v = ((const float4*)(Vg + (size_t)(jt * 32 + j) * Dd))[d4];
            *(float4*)&sV[j * 68 + d4 * 4] = v;
        }
        #pragma unroll
        for (int it = 0; it < 2; it++) {    // sW: 1024 float4
            int idx = tid + it * 512;
            int j = idx >> 5, f4 = idx & 31;
            float4 w = *(const float4*)(Wg + (size_t)(jt * 32 + j) * Ss + f4 * 4);
            *(float4*)&sW[j * 132 + f4 * 4] = w;
        }
        if (tid < 32) {
            float vn = g_Vn[bh * Ss + jt * 32 + tid];
            sVn[tid] = vn;
            sVnS[tid] = sqrtf(fmaxf(vn, 0.0f));
        }
        __syncthreads();
        #pragma unroll 1
        for (int jj = 0; jj < 32; jj++) {
            float wj = sW[jj * 132 + qrow] * rinv;
            float Vn = sVn[jj];
            float vns = sVnS[jj];
            // entry projection of carried state
            float nx = fsqrt_fast(ssn);
            float sx = (nx >= MAXNF) ? MAXNF * __fdividef(1.0f, nx + EPSF) : 1.0f;
            float xn = sx * sx * ssn;
            // y projection (wj >= 0)
            float ny = fmaxf(wj * vns, EPSF);
            float sy = (ny >= MAXNF) ? MAXNF * __fdividef(1.0f, ny + EPSF) : 1.0f;
            float sw = sy * wj;
            float yn = sw * sw * Vn;
            // dot(ws, v) over 16 dims + quad combine
            float v[16];
            const float4* vr = (const float4*)&sV[jj * 68 + sub * 16];
            #pragma unroll
            for (int i = 0; i < 4; i++) {
                float4 t = vr[i];
                v[4 * i] = t.x; v[4 * i + 1] = t.y; v[4 * i + 2] = t.z; v[4 * i + 3] = t.w;
            }
            float d0 = 0.f, d1 = 0.f, d2 = 0.f, d3 = 0.f;
            #pragma unroll
            for (int i = 0; i < 4; i++) {
                d0 = fmaf(ws[4 * i + 0], v[4 * i + 0], d0);
                d1 = fmaf(ws[4 * i + 1], v[4 * i + 1], d1);
                d2 = fmaf(ws[4 * i + 2], v[4 * i + 2], d2);
                d3 = fmaf(ws[4 * i + 3], v[4 * i + 3], d3);
            }
            float dot = (d0 + d1) + (d2 + d3);
            dot += __shfl_xor_sync(0xffffffffu, dot, 1);
            dot += __shfl_xor_sync(0xffffffffu, dot, 2);
            // mobius scalars
            float xy = sx * sw * dot;
            float t2 = fmaf(2.0f, xy, 1.0f);
            float A = t2 + yn;
            float Bc = 1.0f - xn;
            float rden = __fdividef(1.0f, t2 + xn * yn + EPSF);
            float a = A * rden * sx;
            float b = Bc * rden * sw;
            // unprojected update (exit projection deferred to next entry)
            #pragma unroll
            for (int i = 0; i < 16; i++) ws[i] = fmaf(a, ws[i], b * v[i]);
            ssn = fmaf(a * a, ssn, fmaf(2.0f * a * b, dot, b * b * Vn));
        }
    }
    // final exit projection
    float nx = fsqrt_fast(ssn);
    float sfin = (nx >= MAXNF) ? MAXNF * __fdividef(1.0f, nx + EPSF) : 1.0f;
    int b = bh >> 3, h = bh & 7;
    int q = q0 + qrow;
    float* dst = g_att + ((size_t)(b * Ss + q)) * Ee + h * Dd + sub * 16;
    #pragma unroll
    for (int i = 0; i < 4; i++) {
        float4 o = {sfin * ws[4 * i], sfin * ws[4 * i + 1],
                    sfin * ws[4 * i + 2], sfin * ws[4 * i + 3]};
        ((float4*)dst)[i] = o;
    }
}

// ---------------- launch ----------------
extern "C" void kernel_launch(void* const* d_in, const int* in_sizes, int n_in,
                              void* d_out, int out_size) {
    const float* query = (const float*)d_in[0];
    const float* key   = (const float*)d_in[1];
    const float* value = (const float*)d_in[2];
    const float* Wq = (const float*)d_in[3];
    const float* bq = (const float*)d_in[4];
    const float* Wk = (const float*)d_in[5];
    const float* bk = (const float*)d_in[6];
    const float* Wv = (const float*)d_in[7];
    const float* bv = (const float*)d_in[8];
    const float* Wo = (const float*)d_in[9];
    const float* bo = (const float*)d_in[10];
    float* out = (float*)d_out;

    static bool attr_set = false;
    if (!attr_set) {
        cudaFuncSetAttribute(attn_kernel, cudaFuncAttributeMaxDynamicSharedMemorySize,
                             SMEM_ATTN_BYTES);
        attr_set = true;
    }

    // 1: prep
    prep_all<<<8196, 128>>>(query, key, value, Wq, Wk, Wv, Wo, bq, bk, bv, bo);
    // 2: QKV gemm
    gemm_mma<<<dim3(4, 32, 3), 256>>>(0);
    // 3: QKV epilogue
    epilogue<<<dim3(NROW, 3), 128>>>(0, nullptr);
    // 4: attention (capture slot — known quantity)
    attn_kernel<<<BH * 16, 256, SMEM_ATTN_BYTES>>>();
    // 5: scan v4 (4 thr/row, 16 warps/SM)
    scan_kernel<<<128, 512>>>();
    // 6: prep for output linear
    prep_att<<<NROW, 128>>>();
    // 7: output gemm
    gemm_mma<<<dim3(4, 32, 1), 256>>>(1);
    // 8: output epilogue
    epilogue<<<dim3(NROW, 1), 128>>>(1, out);
}

// round 15
// speedup vs baseline: 1.1848x; 1.1848x over previous
#include <cuda_runtime.h>
#include <cuda_bf16.h>
#include <cstdint>

#define EPSF 1e-5f
#define EPS2F 1e-10f
#define MAXNF (1.0f - 1e-5f)
#define EPSD 1e-5
#define MAXND (1.0 - 1e-5)

constexpr int Bb = 4, Ss = 512, Ee = 512, Hh = 8, Dd = 64;
constexpr int NROW = Bb * Ss;   // 2048
constexpr int BH = Bb * Hh;     // 32

// ---------------- scratch ----------------
__device__ float g_t[3 * NROW * Ee];
__device__ float g_c[3 * NROW];
__device__ __nv_bfloat16 g_Xh[3 * NROW * Ee];
__device__ __nv_bfloat16 g_Xl[3 * NROW * Ee];
__device__ __nv_bfloat16 g_Wh[4 * Ee * Ee];
__device__ __nv_bfloat16 g_Wl[4 * Ee * Ee];
__device__ __nv_bfloat16 g_Qh[BH * Ss * Dd];
__device__ __nv_bfloat16 g_Ql[BH * Ss * Dd];
__device__ __nv_bfloat16 g_Kh[BH * Ss * Dd];
__device__ __nv_bfloat16 g_Kl[BH * Ss * Dd];
__device__ float g_V[BH * Ss * Dd];
__device__ float g_qn[BH * Ss];
__device__ float g_kn[BH * Ss];
__device__ float g_Vn[BH * Ss];
__device__ float g_rsum[BH * Ss];
__device__ float g_attnT[(size_t)BH * Ss * Ss];   // [bh][k][q], UNNORMALIZED exp
__device__ float g_att[NROW * Ee];
__device__ float g_pb[4 * Ee];
__device__ float g_byn[4];

// ---------------- reduction helpers (128 threads) ----------------
__device__ __forceinline__ float blockReduceSum128(float v, float* sbuf) {
    #pragma unroll
    for (int o = 16; o > 0; o >>= 1) v += __shfl_xor_sync(0xffffffffu, v, o);
    if ((threadIdx.x & 31) == 0) sbuf[threadIdx.x >> 5] = v;
    __syncthreads();
    float r = sbuf[0] + sbuf[1] + sbuf[2] + sbuf[3];
    __syncthreads();
    return r;
}

__device__ __forceinline__ double blockReduceSumD(double v, double* sbuf) {
    #pragma unroll
    for (int o = 16; o > 0; o >>= 1) v += __shfl_xor_sync(0xffffffffu, v, o);
    if ((threadIdx.x & 31) == 0) sbuf[threadIdx.x >> 5] = v;
    __syncthreads();
    double r = sbuf[0] + sbuf[1] + sbuf[2] + sbuf[3];
    __syncthreads();
    return r;
}

__device__ __forceinline__ float fsqrt_fast(float x) {
    float t = fmaxf(x, EPS2F);
    return t * rsqrtf(t);
}

// ---------------- mma.sync helpers ----------------
__device__ __forceinline__ void ldsm4(uint32_t* r, uint32_t addr) {
    asm volatile("ldmatrix.sync.aligned.m8n8.x4.shared.b16 {%0,%1,%2,%3}, [%4];"
        : "=r"(r[0]), "=r"(r[1]), "=r"(r[2]), "=r"(r[3]) : "r"(addr));
}
__device__ __forceinline__ void mma16816(float* d, const uint32_t* a, uint32_t b0, uint32_t b1) {
    asm volatile("mma.sync.aligned.m16n8k16.row.col.f32.bf16.bf16.f32 "
        "{%0,%1,%2,%3}, {%4,%5,%6,%7}, {%8,%9}, {%0,%1,%2,%3};"
        : "+f"(d[0]), "+f"(d[1]), "+f"(d[2]), "+f"(d[3])
        : "r"(a[0]), "r"(a[1]), "r"(a[2]), "r"(a[3]), "r"(b0), "r"(b1));
}

__device__ __forceinline__ void cvt_hilo(float4 f, __nv_bfloat162& h01, __nv_bfloat162& h23,
                                         __nv_bfloat162& l01, __nv_bfloat162& l23) {
    h01 = __floats2bfloat162_rn(f.x, f.y);
    h23 = __floats2bfloat162_rn(f.z, f.w);
    l01 = __floats2bfloat162_rn(f.x - __bfloat162float(h01.x), f.y - __bfloat162float(h01.y));
    l23 = __floats2bfloat162_rn(f.z - __bfloat162float(h23.x), f.w - __bfloat162float(h23.y));
}

// ---------------- prep_all ----------------
__global__ void prep_all(const float* __restrict__ q, const float* __restrict__ k,
                         const float* __restrict__ v,
                         const float* __restrict__ Wq, const float* __restrict__ Wk,
                         const float* __restrict__ Wv, const float* __restrict__ Wo,
                         const float* __restrict__ bq, const float* __restrict__ bk,
                         const float* __restrict__ bv, const float* __restrict__ bo) {
    __shared__ double sbufd[4];
    __shared__ float sbuff[4];
    int bx = blockIdx.x, tid = threadIdx.x;
    if (bx < 6144) {
        int z = bx >> 11, row = bx & 2047;
        const float* x = z == 0 ? q : z == 1 ? k : v;
        float4 f = ((const float4*)(x + (size_t)row * Ee))[tid];
        double ssp = (double)f.x * f.x + (double)f.y * f.y + (double)f.z * f.z + (double)f.w * f.w;
        double ss1 = blockReduceSumD(ssp, sbufd);
        double n1 = sqrt(fmax(ss1, 1e-10));
        double s1 = (n1 >= MAXND) ? MAXND / (n1 + EPSD) : 1.0;
        double ss2 = s1 * s1 * ss1;
        double n2 = sqrt(fmax(ss2, 1e-10));
        double s2 = (n2 >= MAXND) ? MAXND / (n2 + EPSD) : 1.0;
        double ss3 = s2 * s2 * ss2;
        double n = sqrt(fmax(ss3, 1e-10));
        double ff = (1.0 + EPSD) * atanh(n) / n;
        if (tid == 0) g_c[z * NROW + row] = (float)(ff * s2 * s1);
        __nv_bfloat162 h01, h23, l01, l23;
        cvt_hilo(f, h01, h23, l01, l23);
        size_t off = ((size_t)z * NROW + row) * Ee + tid * 4;
        *(__nv_bfloat162*)(g_Xh + off) = h01; *(__nv_bfloat162*)(g_Xh + off + 2) = h23;
        *(__nv_bfloat162*)(g_Xl + off) = l01; *(__nv_bfloat162*)(g_Xl + off + 2) = l23;
    } else if (bx < 8192) {
        int idx = bx - 6144;
        int w = idx >> 9, r = idx & 511;
        const float* W = w == 0 ? Wq : w == 1 ? Wk : w == 2 ? Wv : Wo;
        float4 f = ((const float4*)(W + (size_t)r * Ee))[tid];
        __nv_bfloat162 h01, h23, l01, l23;
        cvt_hilo(f, h01, h23, l01, l23);
        size_t off = ((size_t)w * Ee + r) * Ee + tid * 4;
        *(__nv_bfloat162*)(g_Wh + off) = h01; *(__nv_bfloat162*)(g_Wh + off + 2) = h23;
        *(__nv_bfloat162*)(g_Wl + off) = l01; *(__nv_bfloat162*)(g_Wl + off + 2) = l23;
    } else {
        int b = bx - 8192;
        const float* bp = b == 0 ? bq : b == 1 ? bk : b == 2 ? bv : bo;
        float4 vv = ((const float4*)bp)[tid];
        float ss = vv.x * vv.x + vv.y * vv.y + vv.z * vv.z + vv.w * vv.w;
        ss = blockReduceSum128(ss, sbuff);
        float norm = sqrtf(fmaxf(ss, EPS2F));
        float s1 = (norm >= MAXNF) ? MAXNF / (norm + EPSF) : 1.0f;
        float4 p; p.x = s1 * vv.x; p.y = s1 * vv.y; p.z = s1 * vv.z; p.w = s1 * vv.w;
        ((float4*)(g_pb + b * Ee))[tid] = p;
        float ss2 = p.x * p.x + p.y * p.y + p.z * p.z + p.w * p.w;
        ss2 = blockReduceSum128(ss2, sbuff);
        if (tid == 0) g_byn[b] = ss2;
    }
}

// ---------------- prep_att ----------------
__global__ void prep_att() {
    __shared__ double sbuf[4];
    int row = blockIdx.x, tid = threadIdx.x;
    float4 f = ((const float4*)(g_att + (size_t)row * Ee))[tid];
    double ssp = (double)f.x * f.x + (double)f.y * f.y + (double)f.z * f.z + (double)f.w * f.w;
    double ss1 = blockReduceSumD(ssp, sbuf);
    double n1 = sqrt(fmax(ss1, 1e-10));
    double s1 = (n1 >= MAXND) ? MAXND / (n1 + EPSD) : 1.0;
    double ss2 = s1 * s1 * ss1;
    double n2 = sqrt(fmax(ss2, 1e-10));
    double s2 = (n2 >= MAXND) ? MAXND / (n2 + EPSD) : 1.0;
    double ss3 = s2 * s2 * ss2;
    double n = sqrt(fmax(ss3, 1e-10));
    double ff = (1.0 + EPSD) * atanh(n) / n;
    if (tid == 0) g_c[row] = (float)(ff * s2 * s1);
    __nv_bfloat162 h01, h23, l01, l23;
    cvt_hilo(f, h01, h23, l01, l23);
    size_t off = (size_t)row * Ee + tid * 4;
    *(__nv_bfloat162*)(g_Xh + off) = h01; *(__nv_bfloat162*)(g_Xh + off + 2) = h23;
    *(__nv_bfloat162*)(g_Xl + off) = l01; *(__nv_bfloat162*)(g_Xl + off + 2) = l23;
}

// ---------------- tensor-core GEMM: 64x128 CTA tile, warp 32x32, 2 CTAs/SM ----------------
constexpr int SPAD = 40;
constexpr int GA_H = 0;
constexpr int GA_L = 64 * SPAD;
constexpr int GB_H = 128 * SPAD;
constexpr int GB_L = 256 * SPAD;

__global__ __launch_bounds__(256, 2) void gemm_mma(int final) {
    __shared__ __align__(16) __nv_bfloat16 sm[384 * SPAD];   // 30720 B

    int tid = threadIdx.x, wid = tid >> 5, lane = tid & 31;
    int z = blockIdx.z;
    int wsel = final ? 3 : z;
    float* T = g_t + (size_t)z * NROW * Ee;
    int n0 = blockIdx.x * 128;
    int m0 = blockIdx.y * 64;

    int wm = wid & 1;
    int wn = wid >> 1;

    float d[2][4][4];
    #pragma unroll
    for (int i = 0; i < 2; i++)
        #pragma unroll
        for (int j = 0; j < 4; j++)
            #pragma unroll
            for (int r = 0; r < 4; r++) d[i][j][r] = 0.0f;

    int rowB = tid & 127;
    const __nv_bfloat16* srcB = ((tid >> 7) ? g_Wl : g_Wh) +
                                ((size_t)wsel * Ee + n0 + rowB) * Ee;
    uint32_t dstB = GB_H + (uint32_t)(tid >> 7) * (128 * SPAD) + rowB * SPAD;
    bool hasA = tid < 128;
    int rowA = tid & 63;
    const __nv_bfloat16* srcA = (((tid >> 6) & 1) ? g_Xl : g_Xh) +
                                ((size_t)z * NROW + m0 + rowA) * Ee;
    uint32_t dstA = (uint32_t)((tid >> 6) & 1) * (64 * SPAD) + rowA * SPAD;

    uint32_t smb = (uint32_t)__cvta_generic_to_shared(sm);
    int lrow = lane & 15;
    int lk8  = (lane >> 4) << 3;

    uint4 rbB[4], rbA[4];
    #pragma unroll
    for (int j = 0; j < 4; j++) rbB[j] = ((const uint4*)srcB)[j];
    if (hasA) {
        #pragma unroll
        for (int j = 0; j < 4; j++) rbA[j] = ((const uint4*)srcA)[j];
    }

    for (int c = 0; c < 16; c++) {
        __syncthreads();
        #pragma unroll
        for (int j = 0; j < 4; j++) *(uint4*)&sm[dstB + j * 8] = rbB[j];
        if (hasA) {
            #pragma unroll
            for (int j = 0; j < 4; j++) *(uint4*)&sm[dstA + j * 8] = rbA[j];
        }
        __syncthreads();
        if (c < 15) {
            #pragma unroll
            for (int j = 0; j < 4; j++) rbB[j] = ((const uint4*)srcB)[(c + 1) * 4 + j];
            if (hasA) {
                #pragma unroll
                for (int j = 0; j < 4; j++) rbA[j] = ((const uint4*)srcA)[(c + 1) * 4 + j];
            }
        }
        #pragma unroll
        for (int ks = 0; ks < 2; ks++) {
            int kcol = ks * 16 + lk8;
            uint32_t ah[2][4], al[2][4], bh[2][4], bl[2][4];
            #pragma unroll
            for (int i = 0; i < 2; i++) {
                ldsm4(ah[i], smb + 2 * (GA_H + (wm * 32 + i * 16 + lrow) * SPAD + kcol));
                ldsm4(al[i], smb + 2 * (GA_L + (wm * 32 + i * 16 + lrow) * SPAD + kcol));
            }
            #pragma unroll
            for (int t = 0; t < 2; t++) {
                ldsm4(bh[t], smb + 2 * (GB_H + (wn * 32 + t * 16 + lrow) * SPAD + kcol));
                ldsm4(bl[t], smb + 2 * (GB_L + (wn * 32 + t * 16 + lrow) * SPAD + kcol));
            }
            #pragma unroll
            for (int i = 0; i < 2; i++)
                #pragma unroll
                for (int j = 0; j < 4; j++) {
                    uint32_t b0h = bh[j >> 1][j & 1], b1h = bh[j >> 1][(j & 1) + 2];
                    mma16816(d[i][j], ah[i], b0h, b1h);
                    mma16816(d[i][j], ah[i], bl[j >> 1][j & 1], bl[j >> 1][(j & 1) + 2]);
                    mma16816(d[i][j], al[i], b0h, b1h);
                }
        }
    }
    #pragma unroll
    for (int i = 0; i < 2; i++) {
        int gr = m0 + wm * 32 + i * 16 + (lane >> 2);
        #pragma unroll
        for (int j = 0; j < 4; j++) {
            int gc = n0 + wn * 32 + j * 8 + (lane & 3) * 2;
            *(float2*)&T[(size_t)gr * Ee + gc]       = make_float2(d[i][j][0], d[i][j][1]);
            *(float2*)&T[(size_t)(gr + 8) * Ee + gc] = make_float2(d[i][j][2], d[i][j][3]);
        }
    }
}

// ---------------- epilogue ----------------
__global__ void epilogue(int final, float* __restrict__ out) {
    __shared__ float sbuf[4];
    int row = blockIdx.x;
    int z = blockIdx.y;
    int tid = threadIdx.x;
    int mode = final ? 0 : z + 1;
    int bidx = final ? 3 : z;
    float c = g_c[z * NROW + row];
    float4 t4 = ((const float4*)(g_t + ((size_t)z * NROW + row) * Ee))[tid];
    t4.x *= c; t4.y *= c; t4.z *= c; t4.w *= c;

    float ss_t = t4.x * t4.x + t4.y * t4.y + t4.z * t4.z + t4.w * t4.w;
    ss_t = blockReduceSum128(ss_t, sbuf);
    float n = fsqrt_fast(ss_t);
    float gg = tanhf(n / (1.0f + EPSF)) * __fdividef(1.0f, n);
    float ss_v = gg * gg * ss_t;
    float nv = fsqrt_fast(ss_v);
    float sr = (nv >= MAXNF) ? MAXNF * __fdividef(1.0f, nv + EPSF) : 1.0f;
    float ss_r = sr * sr * ss_v;
    float nr = fsqrt_fast(ss_r);
    float sx = (nr >= MAXNF) ? MAXNF * __fdividef(1.0f, nr + EPSF) : 1.0f;
    float xn = sx * sx * ss_r;
    float m = gg * sr * sx;

    float4 v4; v4.x = m * t4.x; v4.y = m * t4.y; v4.z = m * t4.z; v4.w = m * t4.w;
    float4 p4 = ((const float4*)(g_pb + bidx * Ee))[tid];
    float xyp = v4.x * p4.x + v4.y * p4.y + v4.z * p4.z + v4.w * p4.w;
    float xy = blockReduceSum128(xyp, sbuf);
    float yn = g_byn[bidx];

    float A = 1.0f + 2.0f * xy + yn;
    float Bc = 1.0f - xn;
    float rden = __fdividef(1.0f, 1.0f + 2.0f * xy + xn * yn + EPSF);
    float4 u4;
    u4.x = (A * v4.x + Bc * p4.x) * rden;
    u4.y = (A * v4.y + Bc * p4.y) * rden;
    u4.z = (A * v4.z + Bc * p4.z) * rden;
    u4.w = (A * v4.w + Bc * p4.w) * rden;

    float ss_u = u4.x * u4.x + u4.y * u4.y + u4.z * u4.z + u4.w * u4.w;
    ss_u = blockReduceSum128(ss_u, sbuf);
    float nu = fsqrt_fast(ss_u);
    float so = (nu >= MAXNF) ? MAXNF * __fdividef(1.0f, nu + EPSF) : 1.0f;
    u4.x *= so; u4.y *= so; u4.z *= so; u4.w *= so;

    if (mode == 0) {
        ((float4*)(out + (size_t)row * Ee))[tid] = u4;
        return;
    }
    float hs = u4.x * u4.x + u4.y * u4.y + u4.z * u4.z + u4.w * u4.w;
    #pragma unroll
    for (int o = 8; o > 0; o >>= 1) hs += __shfl_xor_sync(0xffffffffu, hs, o);
    int h = tid >> 4;
    int bI = row >> 9, sI = row & 511;
    int bh = bI * Hh + h;
    size_t base = ((size_t)bh * Ss + sI) * Dd + (tid & 15) * 4;
    if (mode == 3) {
        *(float4*)(g_V + base) = u4;
        if ((tid & 15) == 0) g_Vn[bh * Ss + sI] = hs;
    } else {
        float nh = fsqrt_fast(hs);
        float sh = (nh >= MAXNF) ? MAXNF * __fdividef(1.0f, nh + EPSF) : 1.0f;
        float4 q4; q4.x = sh * u4.x; q4.y = sh * u4.y; q4.z = sh * u4.z; q4.w = sh * u4.w;
        __nv_bfloat162 h01, h23, l01, l23;
        cvt_hilo(q4, h01, h23, l01, l23);
        __nv_bfloat16* dh = (mode == 1 ? g_Qh : g_Kh) + base;
        __nv_bfloat16* dl = (mode == 1 ? g_Ql : g_Kl) + base;
        *(__nv_bfloat162*)dh = h01; *(__nv_bfloat162*)(dh + 2) = h23;
        *(__nv_bfloat162*)dl = l01; *(__nv_bfloat162*)(dl + 2) = l23;
        float* ndst = (mode == 1) ? g_qn : g_kn;
        if ((tid & 15) == 0) ndst[bh * Ss + sI] = sh * sh * hs;
    }
}

// ---------------- attention: register-S MMA distances + online softmax ----------------
constexpr int QPAD = 72;
constexpr int AOFF_QH = 0;
constexpr int AOFF_QL = 4608;
constexpr int AOFF_KH = 9216;
constexpr int AOFF_KL = 27648;
constexpr int AOFF_KN = 46080;
constexpr int AOFF_QN = 48128;
constexpr int AOFF_RED = 48256;
constexpr int SMEM_ATTN_BYTES = 49280;

__global__ __launch_bounds__(256, 2) void attn_kernel() {
    extern __shared__ char smc[];
    __nv_bfloat16* Kh = (__nv_bfloat16*)(smc + AOFF_KH);
    __nv_bfloat16* Kl = (__nv_bfloat16*)(smc + AOFF_KL);
    float* Pst = (float*)(smc + AOFF_KH);
    float* knS = (float*)(smc + AOFF_KN);
    float* qnS = (float*)(smc + AOFF_QN);
    float* RED = (float*)(smc + AOFF_RED);

    int bh = blockIdx.x >> 4, qt = blockIdx.x & 15;
    int tid = threadIdx.x, wid = tid >> 5, lane = tid & 31;
    int lrow = lane & 15, lk8 = (lane >> 4) << 3;

    for (int i = tid; i < 512; i += 256) knS[i] = g_kn[bh * Ss + i];
    if (tid < 32) qnS[tid] = g_qn[bh * Ss + qt * 32 + tid];

    #pragma unroll
    for (int it = 0; it < 2; it++) {
        int u = tid + it * 256;
        int mat = u >> 8, row = (u >> 3) & 31, c16 = u & 7;
        const uint4* src = (const uint4*)((mat ? g_Ql : g_Qh) +
                            ((size_t)bh * Ss + qt * 32 + row) * Dd) + c16;
        *(uint4*)(smc + (mat ? AOFF_QL : AOFF_QH) + 2 * (row * QPAD + c16 * 8)) = *src;
    }
    __syncthreads();

    uint32_t smb = (uint32_t)__cvta_generic_to_shared(smc);

    uint32_t Ah[2][4][4];
    #pragma unroll
    for (int mm = 0; mm < 2; mm++)
        #pragma unroll
        for (int k = 0; k < 4; k++)
            ldsm4(Ah[mm][k], smb + AOFF_QH + 2 * ((mm * 16 + lrow) * QPAD + k * 16 + lk8));

    float S[4][2][2][4];

    for (int c = 0; c < 4; c++) {
        __syncthreads();
        #pragma unroll
        for (int it = 0; it < 8; it++) {
            int u = tid + it * 256;
            int mat = u >> 10, row = (u >> 3) & 127, c16 = u & 7;
            const uint4* src = (const uint4*)((mat ? g_Kl : g_Kh) +
                                ((size_t)bh * Ss + c * 128 + row) * Dd) + c16;
            *(uint4*)((mat ? Kl : Kh) + row * QPAD + c16 * 8) = *src;
        }
        __syncthreads();

        #pragma unroll
        for (int mm = 0; mm < 2; mm++)
            #pragma unroll
            for (int j = 0; j < 2; j++)
                #pragma unroll
                for (int r = 0; r < 4; r++) S[c][mm][j][r] = 0.0f;

        #pragma unroll
        for (int k = 0; k < 4; k++) {
            uint32_t Bh[4], Bl[4];
            ldsm4(Bh, smb + AOFF_KH + 2 * ((wid * 16 + lrow) * QPAD + k * 16 + lk8));
            ldsm4(Bl, smb + AOFF_KL + 2 * ((wid * 16 + lrow) * QPAD + k * 16 + lk8));
            #pragma unroll
            for (int mm = 0; mm < 2; mm++) {
                uint32_t Alf[4];
                ldsm4(Alf, smb + AOFF_QL + 2 * ((mm * 16 + lrow) * QPAD + k * 16 + lk8));
                #pragma unroll
                for (int j = 0; j < 2; j++) {
                    mma16816(S[c][mm][j], Ah[mm][k], Bh[j], Bh[j + 2]);
                    mma16816(S[c][mm][j], Ah[mm][k], Bl[j], Bl[j + 2]);
                    mma16816(S[c][mm][j], Alf, Bh[j], Bh[j + 2]);
                }
            }
        }
    }

    float qn4[4];
    #pragma unroll
    for (int g = 0; g < 4; g++)
        qn4[g] = qnS[(g >> 1) * 16 + (g & 1) * 8 + (lane >> 2)];
    #pragma unroll
    for (int c = 0; c < 4; c++)
        #pragma unroll
        for (int mm = 0; mm < 2; mm++)
            #pragma unroll
            for (int j = 0; j < 2; j++)
                #pragma unroll
                for (int r = 0; r < 4; r++) {
                    int kk = c * 128 + wid * 16 + j * 8 + (lane & 3) * 2 + (r & 1);
                    float qn = qn4[mm * 2 + (r >> 1)];
                    float kn = knS[kk];
                    float num = fmaxf(qn + kn - 2.0f * S[c][mm][j][r], 0.0f);
                    float den = fmaxf((1.0f - qn) * (1.0f - kn), EPSF);
                    float dd2 = 2.0f * __fdividef(num, den) + EPSF;
                    float s = dd2 * (2.0f + dd2);
                    float sq = s * rsqrtf(fmaxf(s, 1e-30f));
                    S[c][mm][j][r] = -__logf(1.0f + dd2 + sq);
                }

    float mrow[4];
    #pragma unroll
    for (int g = 0; g < 4; g++) {
        int mm = g >> 1, rh = g & 1;
        float ml = -1e30f;
        #pragma unroll
        for (int c = 0; c < 4; c++)
            #pragma unroll
            for (int j = 0; j < 2; j++) {
                ml = fmaxf(ml, S[c][mm][j][rh * 2]);
                ml = fmaxf(ml, S[c][mm][j][rh * 2 + 1]);
            }
        ml = fmaxf(ml, __shfl_xor_sync(0xffffffffu, ml, 1));
        ml = fmaxf(ml, __shfl_xor_sync(0xffffffffu, ml, 2));
        if ((lane & 3) == 0) RED[(mm * 16 + rh * 8 + (lane >> 2)) * 8 + wid] = ml;
    }
    __syncthreads();
    #pragma unroll
    for (int g = 0; g < 4; g++) {
        int row = (g >> 1) * 16 + (g & 1) * 8 + (lane >> 2);
        float m = RED[row * 8];
        #pragma unroll
        for (int w = 1; w < 8; w++) m = fmaxf(m, RED[row * 8 + w]);
        mrow[g] = m;
    }
    __syncthreads();

    float srow[4] = {0.f, 0.f, 0.f, 0.f};
    #pragma unroll
    for (int c = 0; c < 4; c++)
        #pragma unroll
        for (int mm = 0; mm < 2; mm++)
            #pragma unroll
            for (int j = 0; j < 2; j++)
                #pragma unroll
                for (int r = 0; r < 4; r++) {
                    int g = mm * 2 + (r >> 1);
                    float e = __expf(S[c][mm][j][r] - mrow[g]);
                    S[c][mm][j][r] = e;
                    srow[g] += e;
                }
    #pragma unroll
    for (int g = 0; g < 4; g++) {
        float sv = srow[g];
        sv += __shfl_xor_sync(0xffffffffu, sv, 1);
        sv += __shfl_xor_sync(0xffffffffu, sv, 2);
        if ((lane & 3) == 0) RED[((g >> 1) * 16 + (g & 1) * 8 + (lane >> 2)) * 8 + wid] = sv;
    }
    __syncthreads();
    if (wid == 0 && (lane & 3) == 0) {
        #pragma unroll
        for (int g = 0; g < 4; g++) {
            int row = (g >> 1) * 16 + (g & 1) * 8 + (lane >> 2);
            float sv = 0.f;
            #pragma unroll
            for (int w = 0; w < 8; w++) sv += RED[row * 8 + w];
            g_rsum[bh * Ss + qt * 32 + row] = sv;
        }
    }

    float* Og = g_attnT + (size_t)bh * Ss * Ss + qt * 32;
    for (int c = 0; c < 4; c++) {
        __syncthreads();
        #pragma unroll
        for (int mm = 0; mm < 2; mm++)
            #pragma unroll
            for (int j = 0; j < 2; j++)
                #pragma unroll
                for (int r = 0; r < 4; r++) {
                    int kk = wid * 16 + j * 8 + (lane & 3) * 2 + (r & 1);
                    int qi = mm * 16 + (lane >> 2) + 8 * (r >> 1);
                    Pst[kk * 36 + qi] = S[c][mm][j][r];
                }
        __syncthreads();
        #pragma unroll
        for (int i = 0; i < 16; i++) {
            int kkr = wid * 16 + i;
            Og[(size_t)(c * 128 + kkr) * Ss + lane] = Pst[kkr * 36 + lane];
        }
    }
}

// ---------------- scan: 2 thr/row, deferred-exit-projection mobius (R13-proven) ----------------
__global__ __launch_bounds__(256) void scan_kernel() {
    __shared__ float sV[32 * 68];
    __shared__ float sW[32 * 132];
    __shared__ float sVn[32];
    __shared__ float sVnS[32];
    int tid = threadIdx.x;
    int warp = tid >> 5, lane = tid & 31;
    int qrow = warp * 16 + (lane & 15);   // 0..127
    int sub = lane >> 4;                  // 0/1 (32-dim half)
    int bh = blockIdx.x >> 2, qt = blockIdx.x & 3;
    int q0 = qt * 128;
    const float* Vg = g_V + (size_t)bh * Ss * Dd;
    const float* Wg = g_attnT + (size_t)bh * Ss * Ss + q0;

    float rinv = __fdividef(1.0f, g_rsum[bh * Ss + q0 + qrow]);

    float ws[32];
    #pragma unroll
    for (int i = 0; i < 32; i++) ws[i] = 0.0f;
    float ssn = 0.0f;   // ||ws||^2 (ws stored UNPROJECTED; entry proj via sx)

    for (int jt = 0; jt < 16; jt++) {
        __syncthreads();
        #pragma unroll
        for (int it = 0; it < 2; it++) {
            int idx = tid + it * 256;
            int j = idx >> 4, d4 = idx & 15;
            float4 v = ((const float4*)(Vg + (size_t)(jt * 32 + j) * Dd))[d4];
            *(float4*)&sV[j * 68 + d4 * 4] = v;
        }
        #pragma unroll
        for (int it = 0; it < 4; it++) {
            int idx = tid + it * 256;
            int j = idx >> 5, f4 = idx & 31;
            float4 w = *(const float4*)(Wg + (size_t)(jt * 32 + j) * Ss + f4 * 4);
            *(float4*)&sW[j * 132 + f4 * 4] = w;
        }
        if (tid < 32) {
            float vn = g_Vn[bh * Ss + jt * 32 + tid];
            sVn[tid] = vn;
            sVnS[tid] = sqrtf(fmaxf(vn, 0.0f));
        }
        __syncthreads();
        #pragma unroll 1
        for (int jj = 0; jj < 32; jj++) {
            float wj = sW[jj * 132 + qrow] * rinv;
            float Vn = sVn[jj];
            float vns = sVnS[jj];
            // entry projection of carried state (off the dot critical path)
            float nx = fsqrt_fast(ssn);
            float sx = (nx >= MAXNF) ? MAXNF * __fdividef(1.0f, nx + EPSF) : 1.0f;
            float xn = sx * sx * ssn;
            // y projection (wj >= 0)
            float ny = fmaxf(wj * vns, EPSF);
            float sy = (ny >= MAXNF) ? MAXNF * __fdividef(1.0f, ny + EPSF) : 1.0f;
            float sw = sy * wj;
            float yn = sw * sw * Vn;
            // dot(ws, v)
            float v[32];
            const float4* vr = (const float4*)&sV[jj * 68 + sub * 32];
            #pragma unroll
            for (int i = 0; i < 8; i++) {
                float4 t = vr[i];
                v[4 * i] = t.x; v[4 * i + 1] = t.y; v[4 * i + 2] = t.z; v[4 * i + 3] = t.w;
            }
            float d0 = 0.f, d1 = 0.f, d2 = 0.f, d3 = 0.f;
            #pragma unroll
            for (int i = 0; i < 8; i++) {
                d0 = fmaf(ws[4 * i + 0], v[4 * i + 0], d0);
                d1 = fmaf(ws[4 * i + 1], v[4 * i + 1], d1);
                d2 = fmaf(ws[4 * i + 2], v[4 * i + 2], d2);
                d3 = fmaf(ws[4 * i + 3], v[4 * i + 3], d3);
            }
            float dot = (d0 + d1) + (d2 + d3);
            dot += __shfl_xor_sync(0xffffffffu, dot, 16);
            // mobius scalars (single MUFU rcp on chain)
            float xy = sx * sw * dot;
            float t2 = fmaf(2.0f, xy, 1.0f);
            float A = t2 + yn;
            float Bc = 1.0f - xn;
            float rden = __fdividef(1.0f, t2 + xn * yn + EPSF);
            float a = A * rden * sx;
            float b = Bc * rden * sw;
            // unprojected update (exit projection deferred to next entry)
            #pragma unroll
            for (int i = 0; i < 32; i++) ws[i] = fmaf(a, ws[i], b * v[i]);
            ssn = fmaf(a * a, ssn, fmaf(2.0f * a * b, dot, b * b * Vn));
        }
    }
    // final exit projection
    float nx = fsqrt_fast(ssn);
    float sfin = (nx >= MAXNF) ? MAXNF * __fdividef(1.0f, nx + EPSF) : 1.0f;
    int b = bh >> 3, h = bh & 7;
    int q = q0 + qrow;
    float* dst = g_att + ((size_t)(b * Ss + q)) * Ee + h * Dd + sub * 32;
    #pragma unroll
    for (int i = 0; i < 8; i++) {
        float4 o = {sfin * ws[4 * i], sfin * ws[4 * i + 1],
                    sfin * ws[4 * i + 2], sfin * ws[4 * i + 3]};
        ((float4*)dst)[i] = o;
    }
}

// ---------------- launch ----------------
extern "C" void kernel_launch(void* const* d_in, const int* in_sizes, int n_in,
                              void* d_out, int out_size) {
    const float* query = (const float*)d_in[0];
    const float* key   = (const float*)d_in[1];
    const float* value = (const float*)d_in[2];
    const float* Wq = (const float*)d_in[3];
    const float* bq = (const float*)d_in[4];
    const float* Wk = (const float*)d_in[5];
    const float* bk = (const float*)d_in[6];
    const float* Wv = (const float*)d_in[7];
    const float* bv = (const float*)d_in[8];
    const float* Wo = (const float*)d_in[9];
    const float* bo = (const float*)d_in[10];
    float* out = (float*)d_out;

    static bool attr_set = false;
    if (!attr_set) {
        cudaFuncSetAttribute(attn_kernel, cudaFuncAttributeMaxDynamicSharedMemorySize,
                             SMEM_ATTN_BYTES);
        attr_set = true;
    }

    // 1: prep
    prep_all<<<8196, 128>>>(query, key, value, Wq, Wk, Wv, Wo, bq, bk, bv, bo);
    // 2: QKV gemm
    gemm_mma<<<dim3(4, 32, 3), 256>>>(0);
    // 3: QKV epilogue
    epilogue<<<dim3(NROW, 3), 128>>>(0, nullptr);
    // 4: attention
    attn_kernel<<<BH * 16, 256, SMEM_ATTN_BYTES>>>();
    // 5: scan (R13-proven 2 thr/row, no probe)
    scan_kernel<<<128, 256>>>();
    // 6: prep for output linear
    prep_att<<<NROW, 128>>>();
    // 7: output gemm
    gemm_mma<<<dim3(4, 32, 1), 256>>>(1);
    // 8: output epilogue
    epilogue<<<dim3(NROW, 1), 128>>>(1, out);
}

// round 16
// speedup vs baseline: 1.2397x; 1.0463x over previous
#include <cuda_runtime.h>
#include <cuda_bf16.h>
#include <cstdint>

#define EPSF 1e-5f
#define EPS2F 1e-10f
#define MAXNF (1.0f - 1e-5f)
#define EPSD 1e-5
#define MAXND (1.0 - 1e-5)

constexpr int Bb = 4, Ss = 512, Ee = 512, Hh = 8, Dd = 64;
constexpr int NROW = Bb * Ss;   // 2048
constexpr int BH = Bb * Hh;     // 32

// ---------------- scratch ----------------
__device__ float g_t[3 * NROW * Ee];
__device__ float g_c[3 * NROW];
__device__ __nv_bfloat16 g_Xh[3 * NROW * Ee];
__device__ __nv_bfloat16 g_Xl[3 * NROW * Ee];
__device__ __nv_bfloat16 g_Wh[4 * Ee * Ee];
__device__ __nv_bfloat16 g_Wl[4 * Ee * Ee];
__device__ __nv_bfloat16 g_Qh[BH * Ss * Dd];
__device__ __nv_bfloat16 g_Ql[BH * Ss * Dd];
__device__ __nv_bfloat16 g_Kh[BH * Ss * Dd];
__device__ __nv_bfloat16 g_Kl[BH * Ss * Dd];
__device__ float g_V[BH * Ss * Dd];
__device__ float g_qn[BH * Ss];
__device__ float g_kn[BH * Ss];
__device__ float g_Vn[BH * Ss];
__device__ float g_attnT[(size_t)BH * Ss * Ss];   // [bh][k][q], NORMALIZED softmax
__device__ float g_att[NROW * Ee];
__device__ float g_pb[4 * Ee];
__device__ float g_byn[4];

// ---------------- reduction helpers (128 threads) ----------------
__device__ __forceinline__ float blockReduceSum128(float v, float* sbuf) {
    #pragma unroll
    for (int o = 16; o > 0; o >>= 1) v += __shfl_xor_sync(0xffffffffu, v, o);
    if ((threadIdx.x & 31) == 0) sbuf[threadIdx.x >> 5] = v;
    __syncthreads();
    float r = sbuf[0] + sbuf[1] + sbuf[2] + sbuf[3];
    __syncthreads();
    return r;
}

__device__ __forceinline__ double blockReduceSumD(double v, double* sbuf) {
    #pragma unroll
    for (int o = 16; o > 0; o >>= 1) v += __shfl_xor_sync(0xffffffffu, v, o);
    if ((threadIdx.x & 31) == 0) sbuf[threadIdx.x >> 5] = v;
    __syncthreads();
    double r = sbuf[0] + sbuf[1] + sbuf[2] + sbuf[3];
    __syncthreads();
    return r;
}

__device__ __forceinline__ float fsqrt_fast(float x) {
    float t = fmaxf(x, EPS2F);
    return t * rsqrtf(t);
}

// ---------------- mma.sync helpers ----------------
__device__ __forceinline__ void ldsm4(uint32_t* r, uint32_t addr) {
    asm volatile("ldmatrix.sync.aligned.m8n8.x4.shared.b16 {%0,%1,%2,%3}, [%4];"
        : "=r"(r[0]), "=r"(r[1]), "=r"(r[2]), "=r"(r[3]) : "r"(addr));
}
__device__ __forceinline__ void mma16816(float* d, const uint32_t* a, uint32_t b0, uint32_t b1) {
    asm volatile("mma.sync.aligned.m16n8k16.row.col.f32.bf16.bf16.f32 "
        "{%0,%1,%2,%3}, {%4,%5,%6,%7}, {%8,%9}, {%0,%1,%2,%3};"
        : "+f"(d[0]), "+f"(d[1]), "+f"(d[2]), "+f"(d[3])
        : "r"(a[0]), "r"(a[1]), "r"(a[2]), "r"(a[3]), "r"(b0), "r"(b1));
}

__device__ __forceinline__ void cvt_hilo(float4 f, __nv_bfloat162& h01, __nv_bfloat162& h23,
                                         __nv_bfloat162& l01, __nv_bfloat162& l23) {
    h01 = __floats2bfloat162_rn(f.x, f.y);
    h23 = __floats2bfloat162_rn(f.z, f.w);
    l01 = __floats2bfloat162_rn(f.x - __bfloat162float(h01.x), f.y - __bfloat162float(h01.y));
    l23 = __floats2bfloat162_rn(f.z - __bfloat162float(h23.x), f.w - __bfloat162float(h23.y));
}

// ---------------- prep_all ----------------
__global__ void prep_all(const float* __restrict__ q, const float* __restrict__ k,
                         const float* __restrict__ v,
                         const float* __restrict__ Wq, const float* __restrict__ Wk,
                         const float* __restrict__ Wv, const float* __restrict__ Wo,
                         const float* __restrict__ bq, const float* __restrict__ bk,
                         const float* __restrict__ bv, const float* __restrict__ bo) {
    __shared__ double sbufd[4];
    __shared__ float sbuff[4];
    int bx = blockIdx.x, tid = threadIdx.x;
    if (bx < 6144) {
        int z = bx >> 11, row = bx & 2047;
        const float* x = z == 0 ? q : z == 1 ? k : v;
        float4 f = ((const float4*)(x + (size_t)row * Ee))[tid];
        double ssp = (double)f.x * f.x + (double)f.y * f.y + (double)f.z * f.z + (double)f.w * f.w;
        double ss1 = blockReduceSumD(ssp, sbufd);
        double n1 = sqrt(fmax(ss1, 1e-10));
        double s1 = (n1 >= MAXND) ? MAXND / (n1 + EPSD) : 1.0;
        double ss2 = s1 * s1 * ss1;
        double n2 = sqrt(fmax(ss2, 1e-10));
        double s2 = (n2 >= MAXND) ? MAXND / (n2 + EPSD) : 1.0;
        double ss3 = s2 * s2 * ss2;
        double n = sqrt(fmax(ss3, 1e-10));
        double ff = (1.0 + EPSD) * atanh(n) / n;
        if (tid == 0) g_c[z * NROW + row] = (float)(ff * s2 * s1);
        __nv_bfloat162 h01, h23, l01, l23;
        cvt_hilo(f, h01, h23, l01, l23);
        size_t off = ((size_t)z * NROW + row) * Ee + tid * 4;
        *(__nv_bfloat162*)(g_Xh + off) = h01; *(__nv_bfloat162*)(g_Xh + off + 2) = h23;
        *(__nv_bfloat162*)(g_Xl + off) = l01; *(__nv_bfloat162*)(g_Xl + off + 2) = l23;
    } else if (bx < 8192) {
        int idx = bx - 6144;
        int w = idx >> 9, r = idx & 511;
        const float* W = w == 0 ? Wq : w == 1 ? Wk : w == 2 ? Wv : Wo;
        float4 f = ((const float4*)(W + (size_t)r * Ee))[tid];
        __nv_bfloat162 h01, h23, l01, l23;
        cvt_hilo(f, h01, h23, l01, l23);
        size_t off = ((size_t)w * Ee + r) * Ee + tid * 4;
        *(__nv_bfloat162*)(g_Wh + off) = h01; *(__nv_bfloat162*)(g_Wh + off + 2) = h23;
        *(__nv_bfloat162*)(g_Wl + off) = l01; *(__nv_bfloat162*)(g_Wl + off + 2) = l23;
    } else {
        int b = bx - 8192;
        const float* bp = b == 0 ? bq : b == 1 ? bk : b == 2 ? bv : bo;
        float4 vv = ((const float4*)bp)[tid];
        float ss = vv.x * vv.x + vv.y * vv.y + vv.z * vv.z + vv.w * vv.w;
        ss = blockReduceSum128(ss, sbuff);
        float norm = sqrtf(fmaxf(ss, EPS2F));
        float s1 = (norm >= MAXNF) ? MAXNF / (norm + EPSF) : 1.0f;
        float4 p; p.x = s1 * vv.x; p.y = s1 * vv.y; p.z = s1 * vv.z; p.w = s1 * vv.w;
        ((float4*)(g_pb + b * Ee))[tid] = p;
        float ss2 = p.x * p.x + p.y * p.y + p.z * p.z + p.w * p.w;
        ss2 = blockReduceSum128(ss2, sbuff);
        if (tid == 0) g_byn[b] = ss2;
    }
}

// ---------------- prep_att ----------------
__global__ void prep_att() {
    __shared__ double sbuf[4];
    int row = blockIdx.x, tid = threadIdx.x;
    float4 f = ((const float4*)(g_att + (size_t)row * Ee))[tid];
    double ssp = (double)f.x * f.x + (double)f.y * f.y + (double)f.z * f.z + (double)f.w * f.w;
    double ss1 = blockReduceSumD(ssp, sbuf);
    double n1 = sqrt(fmax(ss1, 1e-10));
    double s1 = (n1 >= MAXND) ? MAXND / (n1 + EPSD) : 1.0;
    double ss2 = s1 * s1 * ss1;
    double n2 = sqrt(fmax(ss2, 1e-10));
    double s2 = (n2 >= MAXND) ? MAXND / (n2 + EPSD) : 1.0;
    double ss3 = s2 * s2 * ss2;
    double n = sqrt(fmax(ss3, 1e-10));
    double ff = (1.0 + EPSD) * atanh(n) / n;
    if (tid == 0) g_c[row] = (float)(ff * s2 * s1);
    __nv_bfloat162 h01, h23, l01, l23;
    cvt_hilo(f, h01, h23, l01, l23);
    size_t off = (size_t)row * Ee + tid * 4;
    *(__nv_bfloat162*)(g_Xh + off) = h01; *(__nv_bfloat162*)(g_Xh + off + 2) = h23;
    *(__nv_bfloat162*)(g_Xl + off) = l01; *(__nv_bfloat162*)(g_Xl + off + 2) = l23;
}

// ---------------- tensor-core GEMM: 64x128 CTA tile, warp 32x32, 2 CTAs/SM ----------------
constexpr int SPAD = 40;
constexpr int GA_H = 0;
constexpr int GA_L = 64 * SPAD;
constexpr int GB_H = 128 * SPAD;
constexpr int GB_L = 256 * SPAD;

__global__ __launch_bounds__(256, 2) void gemm_mma(int final) {
    __shared__ __align__(16) __nv_bfloat16 sm[384 * SPAD];   // 30720 B

    int tid = threadIdx.x, wid = tid >> 5, lane = tid & 31;
    int z = blockIdx.z;
    int wsel = final ? 3 : z;
    float* T = g_t + (size_t)z * NROW * Ee;
    int n0 = blockIdx.x * 128;
    int m0 = blockIdx.y * 64;

    int wm = wid & 1;
    int wn = wid >> 1;

    float d[2][4][4];
    #pragma unroll
    for (int i = 0; i < 2; i++)
        #pragma unroll
        for (int j = 0; j < 4; j++)
            #pragma unroll
            for (int r = 0; r < 4; r++) d[i][j][r] = 0.0f;

    int rowB = tid & 127;
    const __nv_bfloat16* srcB = ((tid >> 7) ? g_Wl : g_Wh) +
                                ((size_t)wsel * Ee + n0 + rowB) * Ee;
    uint32_t dstB = GB_H + (uint32_t)(tid >> 7) * (128 * SPAD) + rowB * SPAD;
    bool hasA = tid < 128;
    int rowA = tid & 63;
    const __nv_bfloat16* srcA = (((tid >> 6) & 1) ? g_Xl : g_Xh) +
                                ((size_t)z * NROW + m0 + rowA) * Ee;
    uint32_t dstA = (uint32_t)((tid >> 6) & 1) * (64 * SPAD) + rowA * SPAD;

    uint32_t smb = (uint32_t)__cvta_generic_to_shared(sm);
    int lrow = lane & 15;
    int lk8  = (lane >> 4) << 3;

    uint4 rbB[4], rbA[4];
    #pragma unroll
    for (int j = 0; j < 4; j++) rbB[j] = ((const uint4*)srcB)[j];
    if (hasA) {
        #pragma unroll
        for (int j = 0; j < 4; j++) rbA[j] = ((const uint4*)srcA)[j];
    }

    for (int c = 0; c < 16; c++) {
        __syncthreads();
        #pragma unroll
        for (int j = 0; j < 4; j++) *(uint4*)&sm[dstB + j * 8] = rbB[j];
        if (hasA) {
            #pragma unroll
            for (int j = 0; j < 4; j++) *(uint4*)&sm[dstA + j * 8] = rbA[j];
        }
        __syncthreads();
        if (c < 15) {
            #pragma unroll
            for (int j = 0; j < 4; j++) rbB[j] = ((const uint4*)srcB)[(c + 1) * 4 + j];
            if (hasA) {
                #pragma unroll
                for (int j = 0; j < 4; j++) rbA[j] = ((const uint4*)srcA)[(c + 1) * 4 + j];
            }
        }
        #pragma unroll
        for (int ks = 0; ks < 2; ks++) {
            int kcol = ks * 16 + lk8;
            uint32_t ah[2][4], al[2][4], bh[2][4], bl[2][4];
            #pragma unroll
            for (int i = 0; i < 2; i++) {
                ldsm4(ah[i], smb + 2 * (GA_H + (wm * 32 + i * 16 + lrow) * SPAD + kcol));
                ldsm4(al[i], smb + 2 * (GA_L + (wm * 32 + i * 16 + lrow) * SPAD + kcol));
            }
            #pragma unroll
            for (int t = 0; t < 2; t++) {
                ldsm4(bh[t], smb + 2 * (GB_H + (wn * 32 + t * 16 + lrow) * SPAD + kcol));
                ldsm4(bl[t], smb + 2 * (GB_L + (wn * 32 + t * 16 + lrow) * SPAD + kcol));
            }
            #pragma unroll
            for (int i = 0; i < 2; i++)
                #pragma unroll
                for (int j = 0; j < 4; j++) {
                    uint32_t b0h = bh[j >> 1][j & 1], b1h = bh[j >> 1][(j & 1) + 2];
                    mma16816(d[i][j], ah[i], b0h, b1h);
                    mma16816(d[i][j], ah[i], bl[j >> 1][j & 1], bl[j >> 1][(j & 1) + 2]);
                    mma16816(d[i][j], al[i], b0h, b1h);
                }
        }
    }
    #pragma unroll
    for (int i = 0; i < 2; i++) {
        int gr = m0 + wm * 32 + i * 16 + (lane >> 2);
        #pragma unroll
        for (int j = 0; j < 4; j++) {
            int gc = n0 + wn * 32 + j * 8 + (lane & 3) * 2;
            *(float2*)&T[(size_t)gr * Ee + gc]       = make_float2(d[i][j][0], d[i][j][1]);
            *(float2*)&T[(size_t)(gr + 8) * Ee + gc] = make_float2(d[i][j][2], d[i][j][3]);
        }
    }
}

// ---------------- epilogue ----------------
__global__ void epilogue(int final, float* __restrict__ out) {
    __shared__ float sbuf[4];
    int row = blockIdx.x;
    int z = blockIdx.y;
    int tid = threadIdx.x;
    int mode = final ? 0 : z + 1;
    int bidx = final ? 3 : z;
    float c = g_c[z * NROW + row];
    float4 t4 = ((const float4*)(g_t + ((size_t)z * NROW + row) * Ee))[tid];
    t4.x *= c; t4.y *= c; t4.z *= c; t4.w *= c;

    float ss_t = t4.x * t4.x + t4.y * t4.y + t4.z * t4.z + t4.w * t4.w;
    ss_t = blockReduceSum128(ss_t, sbuf);
    float n = fsqrt_fast(ss_t);
    float gg = tanhf(n / (1.0f + EPSF)) * __fdividef(1.0f, n);
    float ss_v = gg * gg * ss_t;
    float nv = fsqrt_fast(ss_v);
    float sr = (nv >= MAXNF) ? MAXNF * __fdividef(1.0f, nv + EPSF) : 1.0f;
    float ss_r = sr * sr * ss_v;
    float nr = fsqrt_fast(ss_r);
    float sx = (nr >= MAXNF) ? MAXNF * __fdividef(1.0f, nr + EPSF) : 1.0f;
    float xn = sx * sx * ss_r;
    float m = gg * sr * sx;

    float4 v4; v4.x = m * t4.x; v4.y = m * t4.y; v4.z = m * t4.z; v4.w = m * t4.w;
    float4 p4 = ((const float4*)(g_pb + bidx * Ee))[tid];
    float xyp = v4.x * p4.x + v4.y * p4.y + v4.z * p4.z + v4.w * p4.w;
    float xy = blockReduceSum128(xyp, sbuf);
    float yn = g_byn[bidx];

    float A = 1.0f + 2.0f * xy + yn;
    float Bc = 1.0f - xn;
    float rden = __fdividef(1.0f, 1.0f + 2.0f * xy + xn * yn + EPSF);
    float4 u4;
    u4.x = (A * v4.x + Bc * p4.x) * rden;
    u4.y = (A * v4.y + Bc * p4.y) * rden;
    u4.z = (A * v4.z + Bc * p4.z) * rden;
    u4.w = (A * v4.w + Bc * p4.w) * rden;

    float ss_u = u4.x * u4.x + u4.y * u4.y + u4.z * u4.z + u4.w * u4.w;
    ss_u = blockReduceSum128(ss_u, sbuf);
    float nu = fsqrt_fast(ss_u);
    float so = (nu >= MAXNF) ? MAXNF * __fdividef(1.0f, nu + EPSF) : 1.0f;
    u4.x *= so; u4.y *= so; u4.z *= so; u4.w *= so;

    if (mode == 0) {
        ((float4*)(out + (size_t)row * Ee))[tid] = u4;
        return;
    }
    float hs = u4.x * u4.x + u4.y * u4.y + u4.z * u4.z + u4.w * u4.w;
    #pragma unroll
    for (int o = 8; o > 0; o >>= 1) hs += __shfl_xor_sync(0xffffffffu, hs, o);
    int h = tid >> 4;
    int bI = row >> 9, sI = row & 511;
    int bh = bI * Hh + h;
    size_t base = ((size_t)bh * Ss + sI) * Dd + (tid & 15) * 4;
    if (mode == 3) {
        *(float4*)(g_V + base) = u4;
        if ((tid & 15) == 0) g_Vn[bh * Ss + sI] = hs;
    } else {
        float nh = fsqrt_fast(hs);
        float sh = (nh >= MAXNF) ? MAXNF * __fdividef(1.0f, nh + EPSF) : 1.0f;
        float4 q4; q4.x = sh * u4.x; q4.y = sh * u4.y; q4.z = sh * u4.z; q4.w = sh * u4.w;
        __nv_bfloat162 h01, h23, l01, l23;
        cvt_hilo(q4, h01, h23, l01, l23);
        __nv_bfloat16* dh = (mode == 1 ? g_Qh : g_Kh) + base;
        __nv_bfloat16* dl = (mode == 1 ? g_Ql : g_Kl) + base;
        *(__nv_bfloat162*)dh = h01; *(__nv_bfloat162*)(dh + 2) = h23;
        *(__nv_bfloat162*)dl = l01; *(__nv_bfloat162*)(dl + 2) = l23;
        float* ndst = (mode == 1) ? g_qn : g_kn;
        if ((tid & 15) == 0) ndst[bh * Ss + sI] = sh * sh * hs;
    }
}

// ---------------- attention: register-S MMA distances + online softmax ----------------
// Stores NORMALIZED softmax weights (1/rowsum folded into the P store).
constexpr int QPAD = 72;
constexpr int AOFF_QH = 0;
constexpr int AOFF_QL = 4608;
constexpr int AOFF_KH = 9216;
constexpr int AOFF_KL = 27648;
constexpr int AOFF_KN = 46080;
constexpr int AOFF_QN = 48128;
constexpr int AOFF_RED = 48256;
constexpr int AOFF_RINV = 49280;
constexpr int SMEM_ATTN_BYTES = 49408;

__global__ __launch_bounds__(256, 2) void attn_kernel() {
    extern __shared__ char smc[];
    __nv_bfloat16* Kh = (__nv_bfloat16*)(smc + AOFF_KH);
    __nv_bfloat16* Kl = (__nv_bfloat16*)(smc + AOFF_KL);
    float* Pst = (float*)(smc + AOFF_KH);
    float* knS = (float*)(smc + AOFF_KN);
    float* qnS = (float*)(smc + AOFF_QN);
    float* RED = (float*)(smc + AOFF_RED);
    float* sInv = (float*)(smc + AOFF_RINV);

    int bh = blockIdx.x >> 4, qt = blockIdx.x & 15;
    int tid = threadIdx.x, wid = tid >> 5, lane = tid & 31;
    int lrow = lane & 15, lk8 = (lane >> 4) << 3;

    for (int i = tid; i < 512; i += 256) knS[i] = g_kn[bh * Ss + i];
    if (tid < 32) qnS[tid] = g_qn[bh * Ss + qt * 32 + tid];

    #pragma unroll
    for (int it = 0; it < 2; it++) {
        int u = tid + it * 256;
        int mat = u >> 8, row = (u >> 3) & 31, c16 = u & 7;
        const uint4* src = (const uint4*)((mat ? g_Ql : g_Qh) +
                            ((size_t)bh * Ss + qt * 32 + row) * Dd) + c16;
        *(uint4*)(smc + (mat ? AOFF_QL : AOFF_QH) + 2 * (row * QPAD + c16 * 8)) = *src;
    }
    __syncthreads();

    uint32_t smb = (uint32_t)__cvta_generic_to_shared(smc);

    uint32_t Ah[2][4][4];
    #pragma unroll
    for (int mm = 0; mm < 2; mm++)
        #pragma unroll
        for (int k = 0; k < 4; k++)
            ldsm4(Ah[mm][k], smb + AOFF_QH + 2 * ((mm * 16 + lrow) * QPAD + k * 16 + lk8));

    float S[4][2][2][4];

    for (int c = 0; c < 4; c++) {
        __syncthreads();
        #pragma unroll
        for (int it = 0; it < 8; it++) {
            int u = tid + it * 256;
            int mat = u >> 10, row = (u >> 3) & 127, c16 = u & 7;
            const uint4* src = (const uint4*)((mat ? g_Kl : g_Kh) +
                                ((size_t)bh * Ss + c * 128 + row) * Dd) + c16;
            *(uint4*)((mat ? Kl : Kh) + row * QPAD + c16 * 8) = *src;
        }
        __syncthreads();

        #pragma unroll
        for (int mm = 0; mm < 2; mm++)
            #pragma unroll
            for (int j = 0; j < 2; j++)
                #pragma unroll
                for (int r = 0; r < 4; r++) S[c][mm][j][r] = 0.0f;

        #pragma unroll
        for (int k = 0; k < 4; k++) {
            uint32_t Bh[4], Bl[4];
            ldsm4(Bh, smb + AOFF_KH + 2 * ((wid * 16 + lrow) * QPAD + k * 16 + lk8));
            ldsm4(Bl, smb + AOFF_KL + 2 * ((wid * 16 + lrow) * QPAD + k * 16 + lk8));
            #pragma unroll
            for (int mm = 0; mm < 2; mm++) {
                uint32_t Alf[4];
                ldsm4(Alf, smb + AOFF_QL + 2 * ((mm * 16 + lrow) * QPAD + k * 16 + lk8));
                #pragma unroll
                for (int j = 0; j < 2; j++) {
                    mma16816(S[c][mm][j], Ah[mm][k], Bh[j], Bh[j + 2]);
                    mma16816(S[c][mm][j], Ah[mm][k], Bl[j], Bl[j + 2]);
                    mma16816(S[c][mm][j], Alf, Bh[j], Bh[j + 2]);
                }
            }
        }
    }

    float qn4[4];
    #pragma unroll
    for (int g = 0; g < 4; g++)
        qn4[g] = qnS[(g >> 1) * 16 + (g & 1) * 8 + (lane >> 2)];
    #pragma unroll
    for (int c = 0; c < 4; c++)
        #pragma unroll
        for (int mm = 0; mm < 2; mm++)
            #pragma unroll
            for (int j = 0; j < 2; j++)
                #pragma unroll
                for (int r = 0; r < 4; r++) {
                    int kk = c * 128 + wid * 16 + j * 8 + (lane & 3) * 2 + (r & 1);
                    float qn = qn4[mm * 2 + (r >> 1)];
                    float kn = knS[kk];
                    float num = fmaxf(qn + kn - 2.0f * S[c][mm][j][r], 0.0f);
                    float den = fmaxf((1.0f - qn) * (1.0f - kn), EPSF);
                    float dd2 = 2.0f * __fdividef(num, den) + EPSF;
                    float s = dd2 * (2.0f + dd2);
                    float sq = s * rsqrtf(fmaxf(s, 1e-30f));
                    S[c][mm][j][r] = -__logf(1.0f + dd2 + sq);
                }

    float mrow[4];
    #pragma unroll
    for (int g = 0; g < 4; g++) {
        int mm = g >> 1, rh = g & 1;
        float ml = -1e30f;
        #pragma unroll
        for (int c = 0; c < 4; c++)
            #pragma unroll
            for (int j = 0; j < 2; j++) {
                ml = fmaxf(ml, S[c][mm][j][rh * 2]);
                ml = fmaxf(ml, S[c][mm][j][rh * 2 + 1]);
            }
        ml = fmaxf(ml, __shfl_xor_sync(0xffffffffu, ml, 1));
        ml = fmaxf(ml, __shfl_xor_sync(0xffffffffu, ml, 2));
        if ((lane & 3) == 0) RED[(mm * 16 + rh * 8 + (lane >> 2)) * 8 + wid] = ml;
    }
    __syncthreads();
    #pragma unroll
    for (int g = 0; g < 4; g++) {
        int row = (g >> 1) * 16 + (g & 1) * 8 + (lane >> 2);
        float m = RED[row * 8];
        #pragma unroll
        for (int w = 1; w < 8; w++) m = fmaxf(m, RED[row * 8 + w]);
        mrow[g] = m;
    }
    __syncthreads();

    float srow[4] = {0.f, 0.f, 0.f, 0.f};
    #pragma unroll
    for (int c = 0; c < 4; c++)
        #pragma unroll
        for (int mm = 0; mm < 2; mm++)
            #pragma unroll
            for (int j = 0; j < 2; j++)
                #pragma unroll
                for (int r = 0; r < 4; r++) {
                    int g = mm * 2 + (r >> 1);
                    float e = __expf(S[c][mm][j][r] - mrow[g]);
                    S[c][mm][j][r] = e;
                    srow[g] += e;
                }
    #pragma unroll
    for (int g = 0; g < 4; g++) {
        float sv = srow[g];
        sv += __shfl_xor_sync(0xffffffffu, sv, 1);
        sv += __shfl_xor_sync(0xffffffffu, sv, 2);
        if ((lane & 3) == 0) RED[((g >> 1) * 16 + (g & 1) * 8 + (lane >> 2)) * 8 + wid] = sv;
    }
    __syncthreads();
    if (tid < 32) {
        float sv = 0.f;
        #pragma unroll
        for (int w = 0; w < 8; w++) sv += RED[tid * 8 + w];
        sInv[tid] = __fdividef(1.0f, sv);
    }
    // normalized P store per chunk via Pst overlay
    float* Og = g_attnT + (size_t)bh * Ss * Ss + qt * 32;
    for (int c = 0; c < 4; c++) {
        __syncthreads();
        #pragma unroll
        for (int mm = 0; mm < 2; mm++)
            #pragma unroll
            for (int j = 0; j < 2; j++)
                #pragma unroll
                for (int r = 0; r < 4; r++) {
                    int kk = wid * 16 + j * 8 + (lane & 3) * 2 + (r & 1);
                    int qi = mm * 16 + (lane >> 2) + 8 * (r >> 1);
                    Pst[kk * 36 + qi] = S[c][mm][j][r];
                }
        __syncthreads();
        #pragma unroll
        for (int i = 0; i < 16; i++) {
            int kkr = wid * 16 + i;
            Og[(size_t)(c * 128 + kkr) * Ss + lane] = Pst[kkr * 36 + lane] * sInv[lane];
        }
    }
}

// ---------------- scan: 2 thr/row, deferred-beta mobius accumulation ----------------
// ws_true_unproj = cc * ws_stored; update is 1 FMA/elem; refold cc every 8 steps.
__global__ __launch_bounds__(256) void scan_kernel() {
    __shared__ float sV[32 * 68];
    __shared__ float sW[32 * 132];
    __shared__ float sVn[32];
    __shared__ float sVnS[32];
    int tid = threadIdx.x;
    int warp = tid >> 5, lane = tid & 31;
    int qrow = warp * 16 + (lane & 15);   // 0..127
    int sub = lane >> 4;                  // 0/1 (32-dim half)
    int bh = blockIdx.x >> 2, qt = blockIdx.x & 3;
    int q0 = qt * 128;
    const float* Vg = g_V + (size_t)bh * Ss * Dd;
    const float* Wg = g_attnT + (size_t)bh * Ss * Ss + q0;

    float ws[32];
    #pragma unroll
    for (int i = 0; i < 32; i++) ws[i] = 0.0f;
    float ssn = 0.0f;   // ||ws_stored||^2
    float cc = 1.0f;    // ws_true_unproj = cc * ws_stored

    for (int jt = 0; jt < 16; jt++) {
        __syncthreads();
        #pragma unroll
        for (int it = 0; it < 2; it++) {
            int idx = tid + it * 256;
            int j = idx >> 4, d4 = idx & 15;
            float4 v = ((const float4*)(Vg + (size_t)(jt * 32 + j) * Dd))[d4];
            *(float4*)&sV[j * 68 + d4 * 4] = v;
        }
        #pragma unroll
        for (int it = 0; it < 4; it++) {
            int idx = tid + it * 256;
            int j = idx >> 5, f4 = idx & 31;
            float4 w = *(const float4*)(Wg + (size_t)(jt * 32 + j) * Ss + f4 * 4);
            *(float4*)&sW[j * 132 + f4 * 4] = w;
        }
        if (tid < 32) {
            float vn = g_Vn[bh * Ss + jt * 32 + tid];
            sVn[tid] = vn;
            sVnS[tid] = sqrtf(fmaxf(vn, 0.0f));
        }
        __syncthreads();
        #pragma unroll 1
        for (int jj = 0; jj < 32; jj++) {
            float wj = sW[jj * 132 + qrow];     // already softmax-normalized
            float Vn = sVn[jj];
            float vns = sVnS[jj];
            // entry projection of carried true state
            float ssx = cc * cc * ssn;
            float nx = fsqrt_fast(ssx);
            float sx = (nx >= MAXNF) ? MAXNF * __fdividef(1.0f, nx + EPSF) : 1.0f;
            float xn = sx * sx * ssx;
            // y projection (wj >= 0)
            float ny = fmaxf(wj * vns, EPSF);
            float sy = (ny >= MAXNF) ? MAXNF * __fdividef(1.0f, ny + EPSF) : 1.0f;
            float sw = sy * wj;
            float yn = sw * sw * Vn;
            // dot in stored space
            float v[32];
            const float4* vr = (const float4*)&sV[jj * 68 + sub * 32];
            #pragma unroll
            for (int i = 0; i < 8; i++) {
                float4 t = vr[i];
                v[4 * i] = t.x; v[4 * i + 1] = t.y; v[4 * i + 2] = t.z; v[4 * i + 3] = t.w;
            }
            float d0 = 0.f, d1 = 0.f, d2 = 0.f, d3 = 0.f;
            #pragma unroll
            for (int i = 0; i < 8; i++) {
                d0 = fmaf(ws[4 * i + 0], v[4 * i + 0], d0);
                d1 = fmaf(ws[4 * i + 1], v[4 * i + 1], d1);
                d2 = fmaf(ws[4 * i + 2], v[4 * i + 2], d2);
                d3 = fmaf(ws[4 * i + 3], v[4 * i + 3], d3);
            }
            float dot = (d0 + d1) + (d2 + d3);
            dot += __shfl_xor_sync(0xffffffffu, dot, 16);
            // mobius scalars
            float xy = sx * sw * cc * dot;
            float t2 = fmaf(2.0f, xy, 1.0f);
            float A = t2 + yn;
            float Bc = 1.0f - xn;
            float rden = __fdividef(1.0f, t2 + xn * yn + EPSF);
            float den2 = A * sx * cc;
            den2 = copysignf(fmaxf(fabsf(den2), 1e-20f), den2);
            float beta = Bc * sw * __fdividef(1.0f, den2);   // = b / cc_next (rden cancels)
            cc = A * rden * sx * cc;                          // cc_next
            #pragma unroll
            for (int i = 0; i < 32; i++) ws[i] = fmaf(beta, v[i], ws[i]);
            ssn = fmaf(beta, fmaf(beta, Vn, 2.0f * dot), ssn);
            if ((jj & 7) == 7) {   // refold
                #pragma unroll
                for (int i = 0; i < 32; i++) ws[i] *= cc;
                ssn *= cc * cc;
                cc = 1.0f;
            }
        }
    }
    // final exit projection (on true state)
    float ssx = cc * cc * ssn;
    float nx = fsqrt_fast(ssx);
    float sfin = (nx >= MAXNF) ? MAXNF * __fdividef(1.0f, nx + EPSF) : 1.0f;
    float oscale = sfin * cc;
    int b = bh >> 3, h = bh & 7;
    int q = q0 + qrow;
    float* dst = g_att + ((size_t)(b * Ss + q)) * Ee + h * Dd + sub * 32;
    #pragma unroll
    for (int i = 0; i < 8; i++) {
        float4 o = {oscale * ws[4 * i], oscale * ws[4 * i + 1],
                    oscale * ws[4 * i + 2], oscale * ws[4 * i + 3]};
        ((float4*)dst)[i] = o;
    }
}

// ---------------- launch ----------------
extern "C" void kernel_launch(void* const* d_in, const int* in_sizes, int n_in,
                              void* d_out, int out_size) {
    const float* query = (const float*)d_in[0];
    const float* key   = (const float*)d_in[1];
    const float* value = (const float*)d_in[2];
    const float* Wq = (const float*)d_in[3];
    const float* bq = (const float*)d_in[4];
    const float* Wk = (const float*)d_in[5];
    const float* bk = (const float*)d_in[6];
    const float* Wv = (const float*)d_in[7];
    const float* bv = (const float*)d_in[8];
    const float* Wo = (const float*)d_in[9];
    const float* bo = (const float*)d_in[10];
    float* out = (float*)d_out;

    static bool attr_set = false;
    if (!attr_set) {
        cudaFuncSetAttribute(attn_kernel, cudaFuncAttributeMaxDynamicSharedMemorySize,
                             SMEM_ATTN_BYTES);
        attr_set = true;
    }

    prep_all<<<8196, 128>>>(query, key, value, Wq, Wk, Wv, Wo, bq, bk, bv, bo);
    gemm_mma<<<dim3(4, 32, 3), 256>>>(0);
    epilogue<<<dim3(NROW, 3), 128>>>(0, nullptr);
    attn_kernel<<<BH * 16, 256, SMEM_ATTN_BYTES>>>();
    scan_kernel<<<128, 256>>>();
    prep_att<<<NROW, 128>>>();
    gemm_mma<<<dim3(4, 32, 1), 256>>>(1);
    epilogue<<<dim3(NROW, 1), 128>>>(1, out);
}